// round 5
// baseline (speedup 1.0000x reference)
#include <cuda_runtime.h>

#define NN 1024
#define HH 128

typedef unsigned long long u64;
typedef unsigned int u32;

union F2U { u64 u; float2 f; };

__device__ __forceinline__ u64 fma2(u64 a, u64 b, u64 c) {
    u64 d; asm("fma.rn.f32x2 %0, %1, %2, %3;" : "=l"(d) : "l"(a), "l"(b), "l"(c)); return d;
}
__device__ __forceinline__ u64 add2(u64 a, u64 b) {
    u64 d; asm("add.rn.f32x2 %0, %1, %2;" : "=l"(d) : "l"(a), "l"(b)); return d;
}
__device__ __forceinline__ u64 relu2(u64 a) {
    F2U t; t.u = a;
    t.f.x = fmaxf(t.f.x, 0.f);
    t.f.y = fmaxf(t.f.y, 0.f);
    return t.u;
}
__device__ __forceinline__ u64 pack2(float x, float y) {
    F2U t; t.f.x = x; t.f.y = y; return t.u;
}
__device__ __forceinline__ float hsum2(u64 a, u64 b) {
    F2U x, y; x.u = a; y.u = b;
    return (x.f.x + x.f.y) + (y.f.x + y.f.y);
}
__device__ __forceinline__ u32 smem_u32(const void* p) {
    u32 a;
    asm("{ .reg .u64 t; cvta.to.shared.u64 t, %1; cvt.u32.u64 %0, t; }" : "=r"(a) : "l"(p));
    return a;
}
#define CP_ASYNC16(dst, src) \
    asm volatile("cp.async.cg.shared.global [%0], [%1], 16;" :: "r"(dst), "l"(src))
#define CP_COMMIT() asm volatile("cp.async.commit_group;" ::: "memory")
#define CP_WAIT0()  asm volatile("cp.async.wait_group 0;" ::: "memory")

// ---------------- device scratch (no allocations allowed) -------------------
__device__ __align__(16) float g_q[NN * HH];
__device__ __align__(16) float g_k[NN * HH];
__device__ __align__(16) float g_v[NN * HH];
__device__ __align__(16) float g_p[NN * HH];     // p_h(i) = a*x + b*y + c
__device__ __align__(16) float g_rn[NN * HH];    // -(a*x + b*y)
__device__ __align__(16) float g_g[HH];          // g = Wc @ We2
__device__ float g_c0d;                          // Wc . be2 + bc
// split-j partials (8 j-quarters)
__device__ __align__(16) float g_po[8 * NN * HH];
__device__ float g_pm[8 * NN];
__device__ float g_pl[8 * NN];
__device__ float g_pdx[8 * NN];
__device__ float g_pdy[8 * NN];

// ---------------------------------------------------------------------------
// QKV + p/rn + (block 0) fold of the coord path. FFMA2 mainloop.
// ---------------------------------------------------------------------------
__global__ __launch_bounds__(384) void qkv_kernel(
    const float* __restrict__ hin, const float* __restrict__ xin,
    const float* __restrict__ Wq, const float* __restrict__ bq,
    const float* __restrict__ Wk, const float* __restrict__ bk,
    const float* __restrict__ Wv, const float* __restrict__ bv,
    const float* __restrict__ We1, const float* __restrict__ be1,
    const float* __restrict__ We2, const float* __restrict__ be2,
    const float* __restrict__ Wc,  const float* __restrict__ bc) {
    __shared__ __align__(16) float hs[8][132];
    int r0b = blockIdx.x * 8;
    for (int idx = threadIdx.x; idx < 8 * HH; idx += 384)
        hs[idx >> 7][idx & 127] = hin[r0b * HH + idx];
    __syncthreads();

    int o = threadIdx.x;
    const float* W; float bias; float* dst; int col; float scale;
    if (o < 128)      { W = Wq + o * HH;         bias = bq[o];       dst = g_q; col = o;       scale = 0.08838834764831845f; }
    else if (o < 256) { W = Wk + (o - 128) * HH; bias = bk[o - 128]; dst = g_k; col = o - 128; scale = 1.0f; }
    else              { W = Wv + (o - 256) * HH; bias = bv[o - 256]; dst = g_v; col = o - 256; scale = 1.0f; }

    u64 acc[8];
#pragma unroll
    for (int r = 0; r < 8; ++r) acc[r] = 0ull;

    const ulonglong2* W2 = (const ulonglong2*)W;
#pragma unroll 8
    for (int c4 = 0; c4 < 32; ++c4) {
        ulonglong2 w = W2[c4];
#pragma unroll
        for (int r = 0; r < 8; ++r) {
            ulonglong2 hv = ((const ulonglong2*)&hs[r][0])[c4];
            acc[r] = fma2(w.x, hv.x, acc[r]);
            acc[r] = fma2(w.y, hv.y, acc[r]);
        }
    }
#pragma unroll
    for (int r = 0; r < 8; ++r) {
        F2U u; u.u = acc[r];
        dst[(r0b + r) * HH + col] = (u.f.x + u.f.y + bias) * scale;
    }

    if (o < HH) {
        float a = We1[2 * o], b = We1[2 * o + 1], c = be1[o];
#pragma unroll
        for (int r = 0; r < 8; ++r) {
            int row = r0b + r;
            float xx = xin[2 * row], yy = xin[2 * row + 1];
            float base = fmaf(a, xx, b * yy);
            g_p[row * HH + o]  = base + c;
            g_rn[row * HH + o] = -base;
        }
    }

    if (blockIdx.x == 0) {
        if (o < HH) {
            float g = 0.f;
#pragma unroll 16
            for (int e = 0; e < HH; ++e) g = fmaf(Wc[e], We2[e * HH + o], g);
            g_g[o] = g;
        } else if (o == 128) {
            float c0 = bc[0];
#pragma unroll 16
            for (int e = 0; e < HH; ++e) c0 = fmaf(Wc[e], be2[e], c0);
            g_c0d = c0;
        }
    }
}

// ---------------------------------------------------------------------------
// Split-j fused attention + coord diffusion.
// grid = 256 (32 row-groups x 8 j-quarters), 256 threads (8 warps x 4 rows).
// Smem (floats):
//   qp  [32][132] @ 0      (qs in pass1 / ps in pass2, overlaid)
//   ss  [128][36] @ 4224
//   g   [128]     @ 8832
//   buf           @ 8960   pass1: 2 k-tiles (stride 132); pass2: 2 v+rn tiles (stride 268)
// total 26112 floats = 104448 B -> 2 blocks/SM
// ---------------------------------------------------------------------------
#define TSK 132
#define KTILEF (32 * TSK)
#define TSV 268
#define VTILEF (32 * TSV)
#define OFF_QP 0
#define OFF_SS 4224
#define OFF_G  8832
#define OFF_B  8960
#define SMEMF  26112

__device__ __forceinline__ void issue_ktile(u32 dstu, const float* __restrict__ src, int tid) {
#pragma unroll
    for (int l = 0; l < 4; ++l) {
        int c = tid + l * 256;
        int jr = c >> 5, c4 = c & 31;
        CP_ASYNC16(dstu + (u32)((jr * TSK + c4 * 4) * 4), src + jr * HH + c4 * 4);
    }
}
__device__ __forceinline__ void issue_vrtile(u32 dstu, int jrow, int tid) {
#pragma unroll
    for (int l = 0; l < 4; ++l) {
        int c = tid + l * 256;
        int jr = c >> 5, c4 = c & 31;
        CP_ASYNC16(dstu + (u32)((jr * TSV + c4 * 4) * 4), g_v + (jrow + jr) * HH + c4 * 4);
    }
#pragma unroll
    for (int l = 0; l < 4; ++l) {
        int c = tid + l * 256;
        int jr = c >> 5, c4 = c & 31;
        CP_ASYNC16(dstu + (u32)((jr * TSV + 128 + c4 * 4) * 4), g_rn + (jrow + jr) * HH + c4 * 4);
    }
}

__global__ __launch_bounds__(256, 2) void attn_kernel(const float* __restrict__ xin) {
    extern __shared__ float sm[];
    int tid  = threadIdx.x;
    int warp = tid >> 5;
    int lane = tid & 31;
    int rg = blockIdx.x >> 3, jq = blockIdx.x & 7;
    int rbase = rg * 32, jbase = jq * 128;
    int r0 = warp * 4;

    u32 kb_u[2], vr_u[2], qp_u;
    qp_u    = smem_u32(sm + OFF_QP);
    kb_u[0] = smem_u32(sm + OFF_B);
    kb_u[1] = smem_u32(sm + OFF_B + KTILEF);
    vr_u[0] = kb_u[0];
    vr_u[1] = smem_u32(sm + OFF_B + VTILEF);

    // stage q for this block's 32 rows; g vector
    for (int idx = tid; idx < 32 * HH; idx += 256) {
        int r = idx >> 7, c = idx & 127;
        sm[OFF_QP + r * TSK + c] = g_q[(rbase + r) * HH + c];
    }
    if (tid < HH) sm[OFF_G + tid] = g_g[tid];

    // ---- Pass 1: logits (k tiles double-buffered) ----
    issue_ktile(kb_u[0], g_k + jbase * HH, tid);
    CP_COMMIT();

#pragma unroll
    for (int t = 0; t < 4; ++t) {
        CP_WAIT0();
        __syncthreads();
        if (t < 3) {
            issue_ktile(kb_u[(t + 1) & 1], g_k + (jbase + (t + 1) * 32) * HH, tid);
            CP_COMMIT();
        }
        const float* kb = sm + OFF_B + (t & 1) * KTILEF;
        const ulonglong2* kp = (const ulonglong2*)(kb + lane * TSK);
        const ulonglong2* q0 = (const ulonglong2*)(sm + OFF_QP + (r0 + 0) * TSK);
        const ulonglong2* q1 = (const ulonglong2*)(sm + OFF_QP + (r0 + 1) * TSK);
        const ulonglong2* q2 = (const ulonglong2*)(sm + OFF_QP + (r0 + 2) * TSK);
        const ulonglong2* q3 = (const ulonglong2*)(sm + OFF_QP + (r0 + 3) * TSK);
        u64 a00 = 0, a01 = 0, a10 = 0, a11 = 0, a20 = 0, a21 = 0, a30 = 0, a31 = 0;
#pragma unroll 8
        for (int m = 0; m < 32; ++m) {
            ulonglong2 kk = kp[m];
            ulonglong2 t0 = q0[m], t1 = q1[m], t2 = q2[m], t3 = q3[m];
            a00 = fma2(t0.x, kk.x, a00); a01 = fma2(t0.y, kk.y, a01);
            a10 = fma2(t1.x, kk.x, a10); a11 = fma2(t1.y, kk.y, a11);
            a20 = fma2(t2.x, kk.x, a20); a21 = fma2(t2.y, kk.y, a21);
            a30 = fma2(t3.x, kk.x, a30); a31 = fma2(t3.y, kk.y, a31);
        }
        float4 sv;
        sv.x = hsum2(a00, a01);
        sv.y = hsum2(a10, a11);
        sv.z = hsum2(a20, a21);
        sv.w = hsum2(a30, a31);
        *(float4*)(sm + OFF_SS + (t * 32 + lane) * 36 + r0) = sv;
    }

    // all warps done with k buffers AND qs region
    __syncthreads();

    // prefetch vr tile 0 and ps (into qs overlay); overlaps softmax below
    issue_vrtile(vr_u[0], jbase, tid);
#pragma unroll
    for (int l = 0; l < 4; ++l) {
        int c = tid + l * 256;
        int r = c >> 5, c4 = c & 31;
        CP_ASYNC16(qp_u + (u32)((r * TSK + c4 * 4) * 4), g_p + (rbase + r) * HH + c4 * 4);
    }
    CP_COMMIT();

    // ---- local softmax (warp-private rows; unnormalized exp kept in ss) ----
    float m_r[4], l_r[4];
#pragma unroll
    for (int r = 0; r < 4; ++r) {
        int row = r0 + r;
        float s0 = sm[OFF_SS + (lane +  0) * 36 + row];
        float s1 = sm[OFF_SS + (lane + 32) * 36 + row];
        float s2 = sm[OFF_SS + (lane + 64) * 36 + row];
        float s3 = sm[OFF_SS + (lane + 96) * 36 + row];
        float mx = fmaxf(fmaxf(s0, s1), fmaxf(s2, s3));
#pragma unroll
        for (int off = 16; off; off >>= 1) mx = fmaxf(mx, __shfl_xor_sync(0xffffffffu, mx, off));
        float e0 = __expf(s0 - mx), e1 = __expf(s1 - mx);
        float e2 = __expf(s2 - mx), e3 = __expf(s3 - mx);
        sm[OFF_SS + (lane +  0) * 36 + row] = e0;
        sm[OFF_SS + (lane + 32) * 36 + row] = e1;
        sm[OFF_SS + (lane + 64) * 36 + row] = e2;
        sm[OFF_SS + (lane + 96) * 36 + row] = e3;
        float l = (e0 + e1) + (e2 + e3);
#pragma unroll
        for (int off = 16; off; off >>= 1) l += __shfl_xor_sync(0xffffffffu, l, off);
        m_r[r] = mx; l_r[r] = l;
    }

    // ---- Pass 2: P@V + coord, double-buffered combined v|rn tiles ----
    float c0d = g_c0d;
    float2 xi[4];
#pragma unroll
    for (int r = 0; r < 4; ++r) xi[r] = ((const float2*)xin)[rbase + r0 + r];

    u64 o0a = 0, o0b = 0, o1a = 0, o1b = 0, o2a = 0, o2b = 0, o3a = 0, o3b = 0;
    float dxa[4] = {0.f, 0.f, 0.f, 0.f}, dya[4] = {0.f, 0.f, 0.f, 0.f};

#pragma unroll
    for (int t = 0; t < 4; ++t) {
        CP_WAIT0();
        __syncthreads();
        if (t < 3) {
            issue_vrtile(vr_u[(t + 1) & 1], jbase + (t + 1) * 32, tid);
            CP_COMMIT();
        }
        const float* vb = sm + OFF_B + (t & 1) * VTILEF;

        // P @ V : lane = h-chunk (4 floats)
#pragma unroll 8
        for (int jj = 0; jj < 32; ++jj) {
            float4 p4 = *(const float4*)(sm + OFF_SS + (t * 32 + jj) * 36 + r0);
            ulonglong2 vv = *(const ulonglong2*)(vb + jj * TSV + lane * 4);
            u64 pp;
            pp = pack2(p4.x, p4.x); o0a = fma2(pp, vv.x, o0a); o0b = fma2(pp, vv.y, o0b);
            pp = pack2(p4.y, p4.y); o1a = fma2(pp, vv.x, o1a); o1b = fma2(pp, vv.y, o1b);
            pp = pack2(p4.z, p4.z); o2a = fma2(pp, vv.x, o2a); o2b = fma2(pp, vv.y, o2b);
            pp = pack2(p4.w, p4.w); o3a = fma2(pp, vv.x, o3a); o3b = fma2(pp, vv.y, o3b);
        }

        // coord weights: lane = j
        const ulonglong2* rp = (const ulonglong2*)(vb + lane * TSV + 128);
        const ulonglong2* g2 = (const ulonglong2*)(sm + OFF_G);
        const ulonglong2* p0 = (const ulonglong2*)(sm + OFF_QP + (r0 + 0) * TSK);
        const ulonglong2* p1 = (const ulonglong2*)(sm + OFF_QP + (r0 + 1) * TSK);
        const ulonglong2* p2 = (const ulonglong2*)(sm + OFF_QP + (r0 + 2) * TSK);
        const ulonglong2* p3 = (const ulonglong2*)(sm + OFF_QP + (r0 + 3) * TSK);
        u64 cA0 = 0, cB0 = 0, cA1 = 0, cB1 = 0, cA2 = 0, cB2 = 0, cA3 = 0, cB3 = 0;
#pragma unroll 8
        for (int mm = 0; mm < 32; ++mm) {
            ulonglong2 rr = rp[mm];
            ulonglong2 gg = g2[mm];
            ulonglong2 pA = p0[mm];
            cA0 = fma2(relu2(add2(pA.x, rr.x)), gg.x, cA0);
            cB0 = fma2(relu2(add2(pA.y, rr.y)), gg.y, cB0);
            ulonglong2 pB = p1[mm];
            cA1 = fma2(relu2(add2(pB.x, rr.x)), gg.x, cA1);
            cB1 = fma2(relu2(add2(pB.y, rr.y)), gg.y, cB1);
            ulonglong2 pC = p2[mm];
            cA2 = fma2(relu2(add2(pC.x, rr.x)), gg.x, cA2);
            cB2 = fma2(relu2(add2(pC.y, rr.y)), gg.y, cB2);
            ulonglong2 pD = p3[mm];
            cA3 = fma2(relu2(add2(pD.x, rr.x)), gg.x, cA3);
            cB3 = fma2(relu2(add2(pD.y, rr.y)), gg.y, cB3);
        }
        float cw0 = c0d + hsum2(cA0, cB0);
        float cw1 = c0d + hsum2(cA1, cB1);
        float cw2 = c0d + hsum2(cA2, cB2);
        float cw3 = c0d + hsum2(cA3, cB3);

        float4 p4j = *(const float4*)(sm + OFF_SS + (t * 32 + lane) * 36 + r0);
        float2 xj = __ldg((const float2*)xin + jbase + t * 32 + lane);
        float w;
        w = p4j.x * cw0; dxa[0] = fmaf(w, xi[0].x - xj.x, dxa[0]); dya[0] = fmaf(w, xi[0].y - xj.y, dya[0]);
        w = p4j.y * cw1; dxa[1] = fmaf(w, xi[1].x - xj.x, dxa[1]); dya[1] = fmaf(w, xi[1].y - xj.y, dya[1]);
        w = p4j.z * cw2; dxa[2] = fmaf(w, xi[2].x - xj.x, dxa[2]); dya[2] = fmaf(w, xi[2].y - xj.y, dya[2]);
        w = p4j.w * cw3; dxa[3] = fmaf(w, xi[3].x - xj.x, dxa[3]); dya[3] = fmaf(w, xi[3].y - xj.y, dya[3]);
    }

    // ---- write partials ----
    u64 oa[4] = {o0a, o1a, o2a, o3a};
    u64 ob[4] = {o0b, o1b, o2b, o3b};
#pragma unroll
    for (int r = 0; r < 4; ++r) {
        int row = rbase + r0 + r;
        F2U a, b; a.u = oa[r]; b.u = ob[r];
        float4 ov; ov.x = a.f.x; ov.y = a.f.y; ov.z = b.f.x; ov.w = b.f.y;
        ((float4*)g_po)[(jq * NN + row) * 32 + lane] = ov;
        float dx = dxa[r], dy = dya[r];
#pragma unroll
        for (int off = 16; off; off >>= 1) {
            dx += __shfl_xor_sync(0xffffffffu, dx, off);
            dy += __shfl_xor_sync(0xffffffffu, dy, off);
        }
        if (lane == 0) {
            g_pm[jq * NN + row]  = m_r[r];
            g_pl[jq * NN + row]  = l_r[r];
            g_pdx[jq * NN + row] = dx;
            g_pdy[jq * NN + row] = dy;
        }
    }
}

// ---------------------------------------------------------------------------
// Combine 8 j-quarter partials per row. grid 128 x 256 thr, warp = row.
// ---------------------------------------------------------------------------
__global__ __launch_bounds__(256) void combine_kernel(
    const float* __restrict__ hin, const float* __restrict__ xin,
    float* __restrict__ out) {
    int warp = threadIdx.x >> 5, lane = threadIdx.x & 31;
    int row = blockIdx.x * 8 + warp;

    float mq[8];
#pragma unroll
    for (int q = 0; q < 8; ++q) mq[q] = g_pm[q * NN + row];
    float M = mq[0];
#pragma unroll
    for (int q = 1; q < 8; ++q) M = fmaxf(M, mq[q]);
    float eq[8], L = 0.f;
#pragma unroll
    for (int q = 0; q < 8; ++q) {
        eq[q] = __expf(mq[q] - M);
        L = fmaf(eq[q], g_pl[q * NN + row], L);
    }
    float rinv = 1.f / L;

    float4 acc = make_float4(0.f, 0.f, 0.f, 0.f);
#pragma unroll
    for (int q = 0; q < 8; ++q) {
        float4 ov = ((const float4*)g_po)[(q * NN + row) * 32 + lane];
        acc.x = fmaf(eq[q], ov.x, acc.x);
        acc.y = fmaf(eq[q], ov.y, acc.y);
        acc.z = fmaf(eq[q], ov.z, acc.z);
        acc.w = fmaf(eq[q], ov.w, acc.w);
    }
    float4 hv = ((const float4*)hin)[row * 32 + lane];
    float4 o;
    o.x = hv.x + acc.x * rinv;
    o.y = hv.y + acc.y * rinv;
    o.z = hv.z + acc.z * rinv;
    o.w = hv.w + acc.w * rinv;
    ((float4*)out)[row * 32 + lane] = o;

    if (lane == 0) {
        float dx = 0.f, dy = 0.f;
#pragma unroll
        for (int q = 0; q < 8; ++q) {
            dx = fmaf(eq[q], g_pdx[q * NN + row], dx);
            dy = fmaf(eq[q], g_pdy[q * NN + row], dy);
        }
        float2 xi = ((const float2*)xin)[row];
        float2 xo;
        xo.x = xi.x + dx * rinv;
        xo.y = xi.y + dy * rinv;
        ((float2*)(out + NN * HH))[row] = xo;
    }
}

// ---------------------------------------------------------------------------
extern "C" void kernel_launch(void* const* d_in, const int* in_sizes, int n_in,
                              void* d_out, int out_size) {
    (void)in_sizes; (void)n_in; (void)out_size;
    const float* h   = (const float*)d_in[0];
    const float* x   = (const float*)d_in[1];
    // d_in[2] = batch (unused, all zeros)
    const float* Wq  = (const float*)d_in[3];
    const float* bq  = (const float*)d_in[4];
    const float* Wk  = (const float*)d_in[5];
    const float* bk  = (const float*)d_in[6];
    const float* Wv  = (const float*)d_in[7];
    const float* bv  = (const float*)d_in[8];
    const float* We1 = (const float*)d_in[9];
    const float* be1 = (const float*)d_in[10];
    const float* We2 = (const float*)d_in[11];
    const float* be2 = (const float*)d_in[12];
    const float* Wc  = (const float*)d_in[13];
    const float* bc  = (const float*)d_in[14];
    float* out = (float*)d_out;

    static int smem_set = 0;
    if (!smem_set) {
        cudaFuncSetAttribute(attn_kernel, cudaFuncAttributeMaxDynamicSharedMemorySize,
                             SMEMF * 4);
        smem_set = 1;
    }

    qkv_kernel<<<128, 384>>>(h, x, Wq, bq, Wk, bk, Wv, bv,
                             We1, be1, We2, be2, Wc, bc);
    attn_kernel<<<256, 256, SMEMF * 4>>>(x);
    combine_kernel<<<128, 256>>>(h, x, out);
}

// round 6
// speedup vs baseline: 1.5570x; 1.5570x over previous
#include <cuda_runtime.h>

#define NN 1024
#define HH 128

typedef unsigned long long u64;
typedef unsigned int u32;

union F2U { u64 u; float2 f; };

__device__ __forceinline__ u64 fma2(u64 a, u64 b, u64 c) {
    u64 d; asm("fma.rn.f32x2 %0, %1, %2, %3;" : "=l"(d) : "l"(a), "l"(b), "l"(c)); return d;
}
__device__ __forceinline__ u64 add2(u64 a, u64 b) {
    u64 d; asm("add.rn.f32x2 %0, %1, %2;" : "=l"(d) : "l"(a), "l"(b)); return d;
}
__device__ __forceinline__ u64 relu2(u64 a) {
    F2U t; t.u = a;
    t.f.x = fmaxf(t.f.x, 0.f);
    t.f.y = fmaxf(t.f.y, 0.f);
    return t.u;
}
__device__ __forceinline__ u64 pack2(float x, float y) {
    F2U t; t.f.x = x; t.f.y = y; return t.u;
}
__device__ __forceinline__ float hsum2(u64 a, u64 b) {
    F2U x, y; x.u = a; y.u = b;
    return (x.f.x + x.f.y) + (y.f.x + y.f.y);
}
__device__ __forceinline__ u32 smem_u32(const void* p) {
    u32 a;
    asm("{ .reg .u64 t; cvta.to.shared.u64 t, %1; cvt.u32.u64 %0, t; }" : "=r"(a) : "l"(p));
    return a;
}
#define CP_ASYNC16(dst, src) \
    asm volatile("cp.async.cg.shared.global [%0], [%1], 16;" :: "r"(dst), "l"(src))
#define CP_COMMIT() asm volatile("cp.async.commit_group;" ::: "memory")
#define CP_WAIT0()  asm volatile("cp.async.wait_group 0;" ::: "memory")

// ---------------- device scratch (no allocations allowed) -------------------
__device__ __align__(16) float g_q[NN * HH];
__device__ __align__(16) float g_k[NN * HH];
__device__ __align__(16) float g_v[NN * HH];
__device__ __align__(16) float g_p[NN * HH];     // p_h(i) = a*x + b*y + c
__device__ __align__(16) float g_rn[NN * HH];    // -(a*x + b*y)
__device__ __align__(16) float g_g[HH];          // g = Wc @ We2
__device__ float g_c0d;                          // Wc . be2 + bc
// split-j partials (8 j-quarters)
__device__ __align__(16) float g_po[8 * NN * HH];  // unnormalized P@V partial
__device__ float g_pm[8 * NN];                     // local max
__device__ float g_pl[8 * NN];                     // local sum of exp
__device__ float g_pdx[8 * NN];
__device__ float g_pdy[8 * NN];

// ---------------------------------------------------------------------------
// QKV + p/rn + (block 0) fold of the coord path.
// 256 blocks x 4 rows, 384 threads: thread o owns one output col of q|k|v.
// ---------------------------------------------------------------------------
__global__ __launch_bounds__(384) void qkv_kernel(
    const float* __restrict__ hin, const float* __restrict__ xin,
    const float* __restrict__ Wq, const float* __restrict__ bq,
    const float* __restrict__ Wk, const float* __restrict__ bk,
    const float* __restrict__ Wv, const float* __restrict__ bv,
    const float* __restrict__ We1, const float* __restrict__ be1,
    const float* __restrict__ We2, const float* __restrict__ be2,
    const float* __restrict__ Wc,  const float* __restrict__ bc) {
    __shared__ __align__(16) float hs[4][HH];
    int r0 = blockIdx.x * 4;
    for (int idx = threadIdx.x; idx < 4 * HH; idx += 384)
        hs[idx >> 7][idx & 127] = hin[r0 * HH + idx];
    __syncthreads();

    int o = threadIdx.x;
    const float* W; float bias; float* dst; int col; float scale;
    if (o < 128)      { W = Wq + o * HH;         bias = bq[o];       dst = g_q; col = o;       scale = 0.08838834764831845f; }
    else if (o < 256) { W = Wk + (o - 128) * HH; bias = bk[o - 128]; dst = g_k; col = o - 128; scale = 1.0f; }
    else              { W = Wv + (o - 256) * HH; bias = bv[o - 256]; dst = g_v; col = o - 256; scale = 1.0f; }

    float acc[4];
#pragma unroll
    for (int r = 0; r < 4; ++r) acc[r] = bias;

    const float4* W4 = (const float4*)W;
#pragma unroll 8
    for (int c4 = 0; c4 < 32; ++c4) {
        float4 w = W4[c4];
#pragma unroll
        for (int r = 0; r < 4; ++r) {
            float4 hv = ((const float4*)&hs[r][0])[c4];
            acc[r] = fmaf(hv.x, w.x, acc[r]);
            acc[r] = fmaf(hv.y, w.y, acc[r]);
            acc[r] = fmaf(hv.z, w.z, acc[r]);
            acc[r] = fmaf(hv.w, w.w, acc[r]);
        }
    }
#pragma unroll
    for (int r = 0; r < 4; ++r) dst[(r0 + r) * HH + col] = acc[r] * scale;

    if (o < HH) {
        float a = We1[2 * o], b = We1[2 * o + 1], c = be1[o];
#pragma unroll
        for (int r = 0; r < 4; ++r) {
            int row = r0 + r;
            float xx = xin[2 * row], yy = xin[2 * row + 1];
            float base = fmaf(a, xx, b * yy);
            g_p[row * HH + o]  = base + c;
            g_rn[row * HH + o] = -base;
        }
    }

    if (blockIdx.x == 0) {
        if (o < HH) {
            float g = 0.f;
#pragma unroll 16
            for (int e = 0; e < HH; ++e) g = fmaf(Wc[e], We2[e * HH + o], g);
            g_g[o] = g;
        } else if (o == 128) {
            float c0 = bc[0];
#pragma unroll 16
            for (int e = 0; e < HH; ++e) c0 = fmaf(Wc[e], be2[e], c0);
            g_c0d = c0;
        }
    }
}

// ---------------------------------------------------------------------------
// Split-j fused attention + coord diffusion.  (round-4 proven version)
// grid = 256 blocks (32 row-groups x 8 j-quarters), 256 threads (8 warps).
// Each block: 32 rows x 128 j (4 tiles of 32 j). Warp w handles rows w*4..w*4+3.
// Smem layout (floats):
//   qs  [32][132] @ 0
//   ps  [32][132] @ 4224
//   ss  [128][36] @ 8448   (logits -> exp'd probs; [j][row])
//   gsm [128]     @ 13056
//   buf [2 tiles] @ 13184  (pass1: k double-buffer; pass2: v | rn)
// total 21632 floats = 86528 B -> 2 blocks/SM
// ---------------------------------------------------------------------------
#define TS 132
#define TILEF (32 * TS)
#define OFF_QS 0
#define OFF_PS 4224
#define OFF_SS 8448
#define OFF_G  13056
#define OFF_BUF 13184
#define SMEMF 21632

__device__ __forceinline__ void issue_tile(u32 dstbase, const float* __restrict__ src, int tid) {
#pragma unroll
    for (int l = 0; l < 4; ++l) {
        int c = tid + l * 256;
        int jr = c >> 5, c4 = c & 31;
        CP_ASYNC16(dstbase + (u32)((jr * TS + c4 * 4) * 4), src + jr * HH + c4 * 4);
    }
}

__global__ __launch_bounds__(256, 2) void attn_kernel(const float* __restrict__ xin) {
    extern __shared__ float sm[];
    int tid  = threadIdx.x;
    int warp = tid >> 5;
    int lane = tid & 31;
    int rg = blockIdx.x >> 3, jq = blockIdx.x & 7;
    int rbase = rg * 32, jbase = jq * 128;
    int r0 = warp * 4;

    // stage q, p for this block's 32 rows; g vector
    for (int idx = tid; idx < 32 * HH; idx += 256) {
        int r = idx >> 7, c = idx & 127;
        sm[OFF_QS + r * TS + c] = g_q[(rbase + r) * HH + c];
        sm[OFF_PS + r * TS + c] = g_p[(rbase + r) * HH + c];
    }
    if (tid < HH) sm[OFF_G + tid] = g_g[tid];

    u32 buf_u[2];
    buf_u[0] = smem_u32(sm + OFF_BUF);
    buf_u[1] = smem_u32(sm + OFF_BUF + TILEF);

    // ---- Pass 1: logits (k tiles double-buffered) ----
    issue_tile(buf_u[0], g_k + jbase * HH, tid);
    CP_COMMIT();

#pragma unroll
    for (int t = 0; t < 4; ++t) {
        CP_WAIT0();
        __syncthreads();                        // tile t visible; buffers free
        if (t < 3) {
            issue_tile(buf_u[(t + 1) & 1], g_k + (jbase + (t + 1) * 32) * HH, tid);
            CP_COMMIT();
        }
        const float* kb = sm + OFF_BUF + (t & 1) * TILEF;
        const ulonglong2* kp = (const ulonglong2*)(kb + lane * TS);
        const ulonglong2* q0 = (const ulonglong2*)(sm + OFF_QS + (r0 + 0) * TS);
        const ulonglong2* q1 = (const ulonglong2*)(sm + OFF_QS + (r0 + 1) * TS);
        const ulonglong2* q2 = (const ulonglong2*)(sm + OFF_QS + (r0 + 2) * TS);
        const ulonglong2* q3 = (const ulonglong2*)(sm + OFF_QS + (r0 + 3) * TS);
        u64 a00 = 0, a01 = 0, a10 = 0, a11 = 0, a20 = 0, a21 = 0, a30 = 0, a31 = 0;
#pragma unroll 8
        for (int m = 0; m < 32; ++m) {
            ulonglong2 kk = kp[m];
            ulonglong2 t0 = q0[m], t1 = q1[m], t2 = q2[m], t3 = q3[m];
            a00 = fma2(t0.x, kk.x, a00); a01 = fma2(t0.y, kk.y, a01);
            a10 = fma2(t1.x, kk.x, a10); a11 = fma2(t1.y, kk.y, a11);
            a20 = fma2(t2.x, kk.x, a20); a21 = fma2(t2.y, kk.y, a21);
            a30 = fma2(t3.x, kk.x, a30); a31 = fma2(t3.y, kk.y, a31);
        }
        float4 sv;
        sv.x = hsum2(a00, a01);
        sv.y = hsum2(a10, a11);
        sv.z = hsum2(a20, a21);
        sv.w = hsum2(a30, a31);
        *(float4*)(sm + OFF_SS + (t * 32 + lane) * 36 + r0) = sv;
    }

    // ---- local softmax (warp-private rows; unnormalized exp kept in ss) ----
    float m_r[4], l_r[4];
#pragma unroll
    for (int r = 0; r < 4; ++r) {
        int row = r0 + r;
        float s0 = sm[OFF_SS + (lane +  0) * 36 + row];
        float s1 = sm[OFF_SS + (lane + 32) * 36 + row];
        float s2 = sm[OFF_SS + (lane + 64) * 36 + row];
        float s3 = sm[OFF_SS + (lane + 96) * 36 + row];
        float mx = fmaxf(fmaxf(s0, s1), fmaxf(s2, s3));
#pragma unroll
        for (int off = 16; off; off >>= 1) mx = fmaxf(mx, __shfl_xor_sync(0xffffffffu, mx, off));
        float e0 = __expf(s0 - mx), e1 = __expf(s1 - mx);
        float e2 = __expf(s2 - mx), e3 = __expf(s3 - mx);
        sm[OFF_SS + (lane +  0) * 36 + row] = e0;
        sm[OFF_SS + (lane + 32) * 36 + row] = e1;
        sm[OFF_SS + (lane + 64) * 36 + row] = e2;
        sm[OFF_SS + (lane + 96) * 36 + row] = e3;
        float l = (e0 + e1) + (e2 + e3);
#pragma unroll
        for (int off = 16; off; off >>= 1) l += __shfl_xor_sync(0xffffffffu, l, off);
        m_r[r] = mx; l_r[r] = l;
    }

    // ---- Pass 2: P@V + coord (v in slot0, rn in slot1, single-buffered) ----
    float c0d = g_c0d;
    float2 xi[4];
#pragma unroll
    for (int r = 0; r < 4; ++r) xi[r] = ((const float2*)xin)[rbase + r0 + r];

    u64 o0a = 0, o0b = 0, o1a = 0, o1b = 0, o2a = 0, o2b = 0, o3a = 0, o3b = 0;
    float dxa[4] = {0.f, 0.f, 0.f, 0.f}, dya[4] = {0.f, 0.f, 0.f, 0.f};

    __syncthreads();   // all warps done with k buffers before v/rn overwrite

#pragma unroll
    for (int t = 0; t < 4; ++t) {
        issue_tile(buf_u[0], g_v  + (jbase + t * 32) * HH, tid);
        issue_tile(buf_u[1], g_rn + (jbase + t * 32) * HH, tid);
        CP_COMMIT();
        CP_WAIT0();
        __syncthreads();

        const float* vb  = sm + OFF_BUF;
        const float* rnb = sm + OFF_BUF + TILEF;

        // P @ V : lane = h-chunk (4 floats)
#pragma unroll 8
        for (int jj = 0; jj < 32; ++jj) {
            float4 p4 = *(const float4*)(sm + OFF_SS + (t * 32 + jj) * 36 + r0);
            ulonglong2 vv = *(const ulonglong2*)(vb + jj * TS + lane * 4);
            u64 pp;
            pp = pack2(p4.x, p4.x); o0a = fma2(pp, vv.x, o0a); o0b = fma2(pp, vv.y, o0b);
            pp = pack2(p4.y, p4.y); o1a = fma2(pp, vv.x, o1a); o1b = fma2(pp, vv.y, o1b);
            pp = pack2(p4.z, p4.z); o2a = fma2(pp, vv.x, o2a); o2b = fma2(pp, vv.y, o2b);
            pp = pack2(p4.w, p4.w); o3a = fma2(pp, vv.x, o3a); o3b = fma2(pp, vv.y, o3b);
        }

        // coord weights: lane = j
        const ulonglong2* rp = (const ulonglong2*)(rnb + lane * TS);
        const ulonglong2* g2 = (const ulonglong2*)(sm + OFF_G);
        const ulonglong2* p0 = (const ulonglong2*)(sm + OFF_PS + (r0 + 0) * TS);
        const ulonglong2* p1 = (const ulonglong2*)(sm + OFF_PS + (r0 + 1) * TS);
        const ulonglong2* p2 = (const ulonglong2*)(sm + OFF_PS + (r0 + 2) * TS);
        const ulonglong2* p3 = (const ulonglong2*)(sm + OFF_PS + (r0 + 3) * TS);
        u64 cA0 = 0, cB0 = 0, cA1 = 0, cB1 = 0, cA2 = 0, cB2 = 0, cA3 = 0, cB3 = 0;
#pragma unroll 8
        for (int mm = 0; mm < 32; ++mm) {
            ulonglong2 rr = rp[mm];
            ulonglong2 gg = g2[mm];
            ulonglong2 pA = p0[mm];
            cA0 = fma2(relu2(add2(pA.x, rr.x)), gg.x, cA0);
            cB0 = fma2(relu2(add2(pA.y, rr.y)), gg.y, cB0);
            ulonglong2 pB = p1[mm];
            cA1 = fma2(relu2(add2(pB.x, rr.x)), gg.x, cA1);
            cB1 = fma2(relu2(add2(pB.y, rr.y)), gg.y, cB1);
            ulonglong2 pC = p2[mm];
            cA2 = fma2(relu2(add2(pC.x, rr.x)), gg.x, cA2);
            cB2 = fma2(relu2(add2(pC.y, rr.y)), gg.y, cB2);
            ulonglong2 pD = p3[mm];
            cA3 = fma2(relu2(add2(pD.x, rr.x)), gg.x, cA3);
            cB3 = fma2(relu2(add2(pD.y, rr.y)), gg.y, cB3);
        }
        float cw0 = c0d + hsum2(cA0, cB0);
        float cw1 = c0d + hsum2(cA1, cB1);
        float cw2 = c0d + hsum2(cA2, cB2);
        float cw3 = c0d + hsum2(cA3, cB3);

        float4 p4j = *(const float4*)(sm + OFF_SS + (t * 32 + lane) * 36 + r0);
        float2 xj = __ldg((const float2*)xin + jbase + t * 32 + lane);
        float w;
        w = p4j.x * cw0; dxa[0] = fmaf(w, xi[0].x - xj.x, dxa[0]); dya[0] = fmaf(w, xi[0].y - xj.y, dya[0]);
        w = p4j.y * cw1; dxa[1] = fmaf(w, xi[1].x - xj.x, dxa[1]); dya[1] = fmaf(w, xi[1].y - xj.y, dya[1]);
        w = p4j.z * cw2; dxa[2] = fmaf(w, xi[2].x - xj.x, dxa[2]); dya[2] = fmaf(w, xi[2].y - xj.y, dya[2]);
        w = p4j.w * cw3; dxa[3] = fmaf(w, xi[3].x - xj.x, dxa[3]); dya[3] = fmaf(w, xi[3].y - xj.y, dya[3]);

        __syncthreads();   // tile fully consumed before next issue overwrites
    }

    // ---- write partials ----
    u64 oa[4] = {o0a, o1a, o2a, o3a};
    u64 ob[4] = {o0b, o1b, o2b, o3b};
#pragma unroll
    for (int r = 0; r < 4; ++r) {
        int row = rbase + r0 + r;
        F2U a, b; a.u = oa[r]; b.u = ob[r];
        float4 ov; ov.x = a.f.x; ov.y = a.f.y; ov.z = b.f.x; ov.w = b.f.y;
        ((float4*)g_po)[(jq * NN + row) * 32 + lane] = ov;
        float dx = dxa[r], dy = dya[r];
#pragma unroll
        for (int off = 16; off; off >>= 1) {
            dx += __shfl_xor_sync(0xffffffffu, dx, off);
            dy += __shfl_xor_sync(0xffffffffu, dy, off);
        }
        if (lane == 0) {
            g_pm[jq * NN + row]  = m_r[r];
            g_pl[jq * NN + row]  = l_r[r];
            g_pdx[jq * NN + row] = dx;
            g_pdy[jq * NN + row] = dy;
        }
    }
}

// ---------------------------------------------------------------------------
// Combine 8 j-quarter partials per row. grid 128 x 256 thr, warp = row.
// ---------------------------------------------------------------------------
__global__ __launch_bounds__(256) void combine_kernel(
    const float* __restrict__ hin, const float* __restrict__ xin,
    float* __restrict__ out) {
    int warp = threadIdx.x >> 5, lane = threadIdx.x & 31;
    int row = blockIdx.x * 8 + warp;

    float mq[8];
#pragma unroll
    for (int q = 0; q < 8; ++q) mq[q] = g_pm[q * NN + row];
    float M = mq[0];
#pragma unroll
    for (int q = 1; q < 8; ++q) M = fmaxf(M, mq[q]);
    float eq[8], L = 0.f;
#pragma unroll
    for (int q = 0; q < 8; ++q) {
        eq[q] = __expf(mq[q] - M);
        L = fmaf(eq[q], g_pl[q * NN + row], L);
    }
    float rinv = 1.f / L;

    float4 acc = make_float4(0.f, 0.f, 0.f, 0.f);
#pragma unroll
    for (int q = 0; q < 8; ++q) {
        float4 ov = ((const float4*)g_po)[(q * NN + row) * 32 + lane];
        acc.x = fmaf(eq[q], ov.x, acc.x);
        acc.y = fmaf(eq[q], ov.y, acc.y);
        acc.z = fmaf(eq[q], ov.z, acc.z);
        acc.w = fmaf(eq[q], ov.w, acc.w);
    }
    float4 hv = ((const float4*)hin)[row * 32 + lane];
    float4 o;
    o.x = hv.x + acc.x * rinv;
    o.y = hv.y + acc.y * rinv;
    o.z = hv.z + acc.z * rinv;
    o.w = hv.w + acc.w * rinv;
    ((float4*)out)[row * 32 + lane] = o;

    if (lane == 0) {
        float dx = 0.f, dy = 0.f;
#pragma unroll
        for (int q = 0; q < 8; ++q) {
            dx = fmaf(eq[q], g_pdx[q * NN + row], dx);
            dy = fmaf(eq[q], g_pdy[q * NN + row], dy);
        }
        float2 xi = ((const float2*)xin)[row];
        float2 xo;
        xo.x = xi.x + dx * rinv;
        xo.y = xi.y + dy * rinv;
        ((float2*)(out + NN * HH))[row] = xo;
    }
}

// ---------------------------------------------------------------------------
extern "C" void kernel_launch(void* const* d_in, const int* in_sizes, int n_in,
                              void* d_out, int out_size) {
    (void)in_sizes; (void)n_in; (void)out_size;
    const float* h   = (const float*)d_in[0];
    const float* x   = (const float*)d_in[1];
    // d_in[2] = batch (unused, all zeros)
    const float* Wq  = (const float*)d_in[3];
    const float* bq  = (const float*)d_in[4];
    const float* Wk  = (const float*)d_in[5];
    const float* bk  = (const float*)d_in[6];
    const float* Wv  = (const float*)d_in[7];
    const float* bv  = (const float*)d_in[8];
    const float* We1 = (const float*)d_in[9];
    const float* be1 = (const float*)d_in[10];
    const float* We2 = (const float*)d_in[11];
    const float* be2 = (const float*)d_in[12];
    const float* Wc  = (const float*)d_in[13];
    const float* bc  = (const float*)d_in[14];
    float* out = (float*)d_out;

    static int smem_set = 0;
    if (!smem_set) {
        cudaFuncSetAttribute(attn_kernel, cudaFuncAttributeMaxDynamicSharedMemorySize,
                             SMEMF * 4);
        smem_set = 1;
    }

    qkv_kernel<<<256, 384>>>(h, x, Wq, bq, Wk, bk, Wv, bv,
                             We1, be1, We2, be2, Wc, bc);
    attn_kernel<<<256, 256, SMEMF * 4>>>(x);
    combine_kernel<<<128, 256>>>(h, x, out);
}

// round 7
// speedup vs baseline: 1.6902x; 1.0856x over previous
#include <cuda_runtime.h>

#define NN 1024
#define HH 128

typedef unsigned long long u64;
typedef unsigned int u32;

union F2U { u64 u; float2 f; };

__device__ __forceinline__ u64 fma2(u64 a, u64 b, u64 c) {
    u64 d; asm("fma.rn.f32x2 %0, %1, %2, %3;" : "=l"(d) : "l"(a), "l"(b), "l"(c)); return d;
}
__device__ __forceinline__ u64 add2(u64 a, u64 b) {
    u64 d; asm("add.rn.f32x2 %0, %1, %2;" : "=l"(d) : "l"(a), "l"(b)); return d;
}
__device__ __forceinline__ u64 relu2(u64 a) {
    F2U t; t.u = a;
    t.f.x = fmaxf(t.f.x, 0.f);
    t.f.y = fmaxf(t.f.y, 0.f);
    return t.u;
}
__device__ __forceinline__ u64 pack2(float x, float y) {
    F2U t; t.f.x = x; t.f.y = y; return t.u;
}
__device__ __forceinline__ float hsum2(u64 a, u64 b) {
    F2U x, y; x.u = a; y.u = b;
    return (x.f.x + x.f.y) + (y.f.x + y.f.y);
}
__device__ __forceinline__ u32 smem_u32(const void* p) {
    u32 a;
    asm("{ .reg .u64 t; cvta.to.shared.u64 t, %1; cvt.u32.u64 %0, t; }" : "=r"(a) : "l"(p));
    return a;
}
#define CP_ASYNC16(dst, src) \
    asm volatile("cp.async.cg.shared.global [%0], [%1], 16;" :: "r"(dst), "l"(src))
#define CP_COMMIT() asm volatile("cp.async.commit_group;" ::: "memory")
#define CP_WAIT0()  asm volatile("cp.async.wait_group 0;" ::: "memory")

// ---------------- device scratch (no allocations allowed) -------------------
__device__ __align__(16) float g_q[NN * HH];
__device__ __align__(16) float g_k[NN * HH];
__device__ __align__(16) float g_v[NN * HH];
__device__ __align__(16) float g_p[NN * HH];     // p_h(i) = a*x + b*y + c
__device__ __align__(16) float g_rn[NN * HH];    // -(a*x + b*y)
__device__ __align__(16) float g_g[HH];          // g = Wc @ We2
__device__ float g_c0d;                          // Wc . be2 + bc
// split-j partials (8 j-quarters)
__device__ __align__(16) float g_po[8 * NN * HH];  // unnormalized P@V partial
__device__ float g_pm[8 * NN];                     // local max
__device__ float g_pl[8 * NN];                     // local sum of exp
__device__ float g_pdx[8 * NN];
__device__ float g_pdy[8 * NN];

// ---------------------------------------------------------------------------
// QKV + p/rn + (block 0) fold of the coord path.
// grid = 384 blocks (mat = bid>>7 in {q,k,v}, row-group = bid&127 -> 8 rows),
// 128 threads: thread o owns output column o of its matrix for 8 rows.
// ---------------------------------------------------------------------------
__global__ __launch_bounds__(128) void qkv_kernel(
    const float* __restrict__ hin, const float* __restrict__ xin,
    const float* __restrict__ Wq, const float* __restrict__ bq,
    const float* __restrict__ Wk, const float* __restrict__ bk,
    const float* __restrict__ Wv, const float* __restrict__ bv,
    const float* __restrict__ We1, const float* __restrict__ be1,
    const float* __restrict__ We2, const float* __restrict__ be2,
    const float* __restrict__ Wc,  const float* __restrict__ bc) {
    __shared__ __align__(16) float hs[8][HH];
    int mat = blockIdx.x >> 7;        // 0=q, 1=k, 2=v
    int r0  = (blockIdx.x & 127) * 8;

    for (int idx = threadIdx.x; idx < 8 * HH / 4; idx += 128)
        ((float4*)hs)[idx] = ((const float4*)(hin + r0 * HH))[idx];
    __syncthreads();

    int o = threadIdx.x;
    const float* W; float bias; float* dst; float scale;
    if (mat == 0)      { W = Wq + o * HH; bias = bq[o]; dst = g_q; scale = 0.08838834764831845f; }
    else if (mat == 1) { W = Wk + o * HH; bias = bk[o]; dst = g_k; scale = 1.0f; }
    else               { W = Wv + o * HH; bias = bv[o]; dst = g_v; scale = 1.0f; }

    float acc[8];
#pragma unroll
    for (int r = 0; r < 8; ++r) acc[r] = bias;

    const float4* W4 = (const float4*)W;
#pragma unroll 8
    for (int c4 = 0; c4 < 32; ++c4) {
        float4 w = W4[c4];
#pragma unroll
        for (int r = 0; r < 8; ++r) {
            float4 hv = ((const float4*)&hs[r][0])[c4];
            acc[r] = fmaf(hv.x, w.x, acc[r]);
            acc[r] = fmaf(hv.y, w.y, acc[r]);
            acc[r] = fmaf(hv.z, w.z, acc[r]);
            acc[r] = fmaf(hv.w, w.w, acc[r]);
        }
    }
#pragma unroll
    for (int r = 0; r < 8; ++r) dst[(r0 + r) * HH + o] = acc[r] * scale;

    // p / rn for these 8 rows (q-matrix blocks only)
    if (mat == 0) {
        float a = We1[2 * o], b = We1[2 * o + 1], c = be1[o];
#pragma unroll
        for (int r = 0; r < 8; ++r) {
            int row = r0 + r;
            float xx = xin[2 * row], yy = xin[2 * row + 1];
            float base = fmaf(a, xx, b * yy);
            g_p[row * HH + o]  = base + c;
            g_rn[row * HH + o] = -base;
        }
    }

    // fold (single block): g = Wc @ We2, c0 = Wc . be2 + bc
    if (blockIdx.x == 256) {          // first v block: all threads also fold
        float g = 0.f;
#pragma unroll 16
        for (int e = 0; e < HH; ++e) g = fmaf(Wc[e], We2[e * HH + o], g);
        g_g[o] = g;
        if (o == 0) {
            float c0 = bc[0];
#pragma unroll 16
            for (int e = 0; e < HH; ++e) c0 = fmaf(Wc[e], be2[e], c0);
            g_c0d = c0;
        }
    }
}

// ---------------------------------------------------------------------------
// Split-j fused attention + coord diffusion.  (round-4 proven version)
// grid = 256 blocks (32 row-groups x 8 j-quarters), 256 threads (8 warps).
// Each block: 32 rows x 128 j (4 tiles of 32 j). Warp w handles rows w*4..w*4+3.
// Smem layout (floats):
//   qs  [32][132] @ 0
//   ps  [32][132] @ 4224
//   ss  [128][36] @ 8448   (logits -> exp'd probs; [j][row])
//   gsm [128]     @ 13056
//   buf [2 tiles] @ 13184  (pass1: k double-buffer; pass2: v | rn)
// total 21632 floats = 86528 B -> 2 blocks/SM
// ---------------------------------------------------------------------------
#define TS 132
#define TILEF (32 * TS)
#define OFF_QS 0
#define OFF_PS 4224
#define OFF_SS 8448
#define OFF_G  13056
#define OFF_BUF 13184
#define SMEMF 21632

__device__ __forceinline__ void issue_tile(u32 dstbase, const float* __restrict__ src, int tid) {
#pragma unroll
    for (int l = 0; l < 4; ++l) {
        int c = tid + l * 256;
        int jr = c >> 5, c4 = c & 31;
        CP_ASYNC16(dstbase + (u32)((jr * TS + c4 * 4) * 4), src + jr * HH + c4 * 4);
    }
}

__global__ __launch_bounds__(256, 2) void attn_kernel(const float* __restrict__ xin) {
    extern __shared__ float sm[];
    int tid  = threadIdx.x;
    int warp = tid >> 5;
    int lane = tid & 31;
    int rg = blockIdx.x >> 3, jq = blockIdx.x & 7;
    int rbase = rg * 32, jbase = jq * 128;
    int r0 = warp * 4;

    // stage q, p for this block's 32 rows; g vector
    for (int idx = tid; idx < 32 * HH; idx += 256) {
        int r = idx >> 7, c = idx & 127;
        sm[OFF_QS + r * TS + c] = g_q[(rbase + r) * HH + c];
        sm[OFF_PS + r * TS + c] = g_p[(rbase + r) * HH + c];
    }
    if (tid < HH) sm[OFF_G + tid] = g_g[tid];

    u32 buf_u[2];
    buf_u[0] = smem_u32(sm + OFF_BUF);
    buf_u[1] = smem_u32(sm + OFF_BUF + TILEF);

    // ---- Pass 1: logits (k tiles double-buffered) ----
    issue_tile(buf_u[0], g_k + jbase * HH, tid);
    CP_COMMIT();

#pragma unroll
    for (int t = 0; t < 4; ++t) {
        CP_WAIT0();
        __syncthreads();                        // tile t visible; buffers free
        if (t < 3) {
            issue_tile(buf_u[(t + 1) & 1], g_k + (jbase + (t + 1) * 32) * HH, tid);
            CP_COMMIT();
        }
        const float* kb = sm + OFF_BUF + (t & 1) * TILEF;
        const ulonglong2* kp = (const ulonglong2*)(kb + lane * TS);
        const ulonglong2* q0 = (const ulonglong2*)(sm + OFF_QS + (r0 + 0) * TS);
        const ulonglong2* q1 = (const ulonglong2*)(sm + OFF_QS + (r0 + 1) * TS);
        const ulonglong2* q2 = (const ulonglong2*)(sm + OFF_QS + (r0 + 2) * TS);
        const ulonglong2* q3 = (const ulonglong2*)(sm + OFF_QS + (r0 + 3) * TS);
        u64 a00 = 0, a01 = 0, a10 = 0, a11 = 0, a20 = 0, a21 = 0, a30 = 0, a31 = 0;
#pragma unroll 8
        for (int m = 0; m < 32; ++m) {
            ulonglong2 kk = kp[m];
            ulonglong2 t0 = q0[m], t1 = q1[m], t2 = q2[m], t3 = q3[m];
            a00 = fma2(t0.x, kk.x, a00); a01 = fma2(t0.y, kk.y, a01);
            a10 = fma2(t1.x, kk.x, a10); a11 = fma2(t1.y, kk.y, a11);
            a20 = fma2(t2.x, kk.x, a20); a21 = fma2(t2.y, kk.y, a21);
            a30 = fma2(t3.x, kk.x, a30); a31 = fma2(t3.y, kk.y, a31);
        }
        float4 sv;
        sv.x = hsum2(a00, a01);
        sv.y = hsum2(a10, a11);
        sv.z = hsum2(a20, a21);
        sv.w = hsum2(a30, a31);
        *(float4*)(sm + OFF_SS + (t * 32 + lane) * 36 + r0) = sv;
    }

    // ---- local softmax (warp-private rows; unnormalized exp kept in ss) ----
    float m_r[4], l_r[4];
#pragma unroll
    for (int r = 0; r < 4; ++r) {
        int row = r0 + r;
        float s0 = sm[OFF_SS + (lane +  0) * 36 + row];
        float s1 = sm[OFF_SS + (lane + 32) * 36 + row];
        float s2 = sm[OFF_SS + (lane + 64) * 36 + row];
        float s3 = sm[OFF_SS + (lane + 96) * 36 + row];
        float mx = fmaxf(fmaxf(s0, s1), fmaxf(s2, s3));
#pragma unroll
        for (int off = 16; off; off >>= 1) mx = fmaxf(mx, __shfl_xor_sync(0xffffffffu, mx, off));
        float e0 = __expf(s0 - mx), e1 = __expf(s1 - mx);
        float e2 = __expf(s2 - mx), e3 = __expf(s3 - mx);
        sm[OFF_SS + (lane +  0) * 36 + row] = e0;
        sm[OFF_SS + (lane + 32) * 36 + row] = e1;
        sm[OFF_SS + (lane + 64) * 36 + row] = e2;
        sm[OFF_SS + (lane + 96) * 36 + row] = e3;
        float l = (e0 + e1) + (e2 + e3);
#pragma unroll
        for (int off = 16; off; off >>= 1) l += __shfl_xor_sync(0xffffffffu, l, off);
        m_r[r] = mx; l_r[r] = l;
    }

    // ---- Pass 2: P@V + coord (v in slot0, rn in slot1, single-buffered) ----
    float c0d = g_c0d;
    float2 xi[4];
#pragma unroll
    for (int r = 0; r < 4; ++r) xi[r] = ((const float2*)xin)[rbase + r0 + r];

    u64 o0a = 0, o0b = 0, o1a = 0, o1b = 0, o2a = 0, o2b = 0, o3a = 0, o3b = 0;
    float dxa[4] = {0.f, 0.f, 0.f, 0.f}, dya[4] = {0.f, 0.f, 0.f, 0.f};

    __syncthreads();   // all warps done with k buffers before v/rn overwrite

#pragma unroll
    for (int t = 0; t < 4; ++t) {
        issue_tile(buf_u[0], g_v  + (jbase + t * 32) * HH, tid);
        issue_tile(buf_u[1], g_rn + (jbase + t * 32) * HH, tid);
        CP_COMMIT();
        CP_WAIT0();
        __syncthreads();

        const float* vb  = sm + OFF_BUF;
        const float* rnb = sm + OFF_BUF + TILEF;

        // P @ V : lane = h-chunk (4 floats)
#pragma unroll 8
        for (int jj = 0; jj < 32; ++jj) {
            float4 p4 = *(const float4*)(sm + OFF_SS + (t * 32 + jj) * 36 + r0);
            ulonglong2 vv = *(const ulonglong2*)(vb + jj * TS + lane * 4);
            u64 pp;
            pp = pack2(p4.x, p4.x); o0a = fma2(pp, vv.x, o0a); o0b = fma2(pp, vv.y, o0b);
            pp = pack2(p4.y, p4.y); o1a = fma2(pp, vv.x, o1a); o1b = fma2(pp, vv.y, o1b);
            pp = pack2(p4.z, p4.z); o2a = fma2(pp, vv.x, o2a); o2b = fma2(pp, vv.y, o2b);
            pp = pack2(p4.w, p4.w); o3a = fma2(pp, vv.x, o3a); o3b = fma2(pp, vv.y, o3b);
        }

        // coord weights: lane = j
        const ulonglong2* rp = (const ulonglong2*)(rnb + lane * TS);
        const ulonglong2* g2 = (const ulonglong2*)(sm + OFF_G);
        const ulonglong2* p0 = (const ulonglong2*)(sm + OFF_PS + (r0 + 0) * TS);
        const ulonglong2* p1 = (const ulonglong2*)(sm + OFF_PS + (r0 + 1) * TS);
        const ulonglong2* p2 = (const ulonglong2*)(sm + OFF_PS + (r0 + 2) * TS);
        const ulonglong2* p3 = (const ulonglong2*)(sm + OFF_PS + (r0 + 3) * TS);
        u64 cA0 = 0, cB0 = 0, cA1 = 0, cB1 = 0, cA2 = 0, cB2 = 0, cA3 = 0, cB3 = 0;
#pragma unroll 8
        for (int mm = 0; mm < 32; ++mm) {
            ulonglong2 rr = rp[mm];
            ulonglong2 gg = g2[mm];
            ulonglong2 pA = p0[mm];
            cA0 = fma2(relu2(add2(pA.x, rr.x)), gg.x, cA0);
            cB0 = fma2(relu2(add2(pA.y, rr.y)), gg.y, cB0);
            ulonglong2 pB = p1[mm];
            cA1 = fma2(relu2(add2(pB.x, rr.x)), gg.x, cA1);
            cB1 = fma2(relu2(add2(pB.y, rr.y)), gg.y, cB1);
            ulonglong2 pC = p2[mm];
            cA2 = fma2(relu2(add2(pC.x, rr.x)), gg.x, cA2);
            cB2 = fma2(relu2(add2(pC.y, rr.y)), gg.y, cB2);
            ulonglong2 pD = p3[mm];
            cA3 = fma2(relu2(add2(pD.x, rr.x)), gg.x, cA3);
            cB3 = fma2(relu2(add2(pD.y, rr.y)), gg.y, cB3);
        }
        float cw0 = c0d + hsum2(cA0, cB0);
        float cw1 = c0d + hsum2(cA1, cB1);
        float cw2 = c0d + hsum2(cA2, cB2);
        float cw3 = c0d + hsum2(cA3, cB3);

        float4 p4j = *(const float4*)(sm + OFF_SS + (t * 32 + lane) * 36 + r0);
        float2 xj = __ldg((const float2*)xin + jbase + t * 32 + lane);
        float w;
        w = p4j.x * cw0; dxa[0] = fmaf(w, xi[0].x - xj.x, dxa[0]); dya[0] = fmaf(w, xi[0].y - xj.y, dya[0]);
        w = p4j.y * cw1; dxa[1] = fmaf(w, xi[1].x - xj.x, dxa[1]); dya[1] = fmaf(w, xi[1].y - xj.y, dya[1]);
        w = p4j.z * cw2; dxa[2] = fmaf(w, xi[2].x - xj.x, dxa[2]); dya[2] = fmaf(w, xi[2].y - xj.y, dya[2]);
        w = p4j.w * cw3; dxa[3] = fmaf(w, xi[3].x - xj.x, dxa[3]); dya[3] = fmaf(w, xi[3].y - xj.y, dya[3]);

        __syncthreads();   // tile fully consumed before next issue overwrites
    }

    // ---- write partials ----
    u64 oa[4] = {o0a, o1a, o2a, o3a};
    u64 ob[4] = {o0b, o1b, o2b, o3b};
#pragma unroll
    for (int r = 0; r < 4; ++r) {
        int row = rbase + r0 + r;
        F2U a, b; a.u = oa[r]; b.u = ob[r];
        float4 ov; ov.x = a.f.x; ov.y = a.f.y; ov.z = b.f.x; ov.w = b.f.y;
        ((float4*)g_po)[(jq * NN + row) * 32 + lane] = ov;
        float dx = dxa[r], dy = dya[r];
#pragma unroll
        for (int off = 16; off; off >>= 1) {
            dx += __shfl_xor_sync(0xffffffffu, dx, off);
            dy += __shfl_xor_sync(0xffffffffu, dy, off);
        }
        if (lane == 0) {
            g_pm[jq * NN + row]  = m_r[r];
            g_pl[jq * NN + row]  = l_r[r];
            g_pdx[jq * NN + row] = dx;
            g_pdy[jq * NN + row] = dy;
        }
    }
}

// ---------------------------------------------------------------------------
// Combine 8 j-quarter partials per row. grid 128 x 256 thr, warp = row.
// ---------------------------------------------------------------------------
__global__ __launch_bounds__(256) void combine_kernel(
    const float* __restrict__ hin, const float* __restrict__ xin,
    float* __restrict__ out) {
    int warp = threadIdx.x >> 5, lane = threadIdx.x & 31;
    int row = blockIdx.x * 8 + warp;

    float mq[8];
#pragma unroll
    for (int q = 0; q < 8; ++q) mq[q] = g_pm[q * NN + row];
    float M = mq[0];
#pragma unroll
    for (int q = 1; q < 8; ++q) M = fmaxf(M, mq[q]);
    float eq[8], L = 0.f;
#pragma unroll
    for (int q = 0; q < 8; ++q) {
        eq[q] = __expf(mq[q] - M);
        L = fmaf(eq[q], g_pl[q * NN + row], L);
    }
    float rinv = 1.f / L;

    float4 acc = make_float4(0.f, 0.f, 0.f, 0.f);
#pragma unroll
    for (int q = 0; q < 8; ++q) {
        float4 ov = ((const float4*)g_po)[(q * NN + row) * 32 + lane];
        acc.x = fmaf(eq[q], ov.x, acc.x);
        acc.y = fmaf(eq[q], ov.y, acc.y);
        acc.z = fmaf(eq[q], ov.z, acc.z);
        acc.w = fmaf(eq[q], ov.w, acc.w);
    }
    float4 hv = ((const float4*)hin)[row * 32 + lane];
    float4 o;
    o.x = hv.x + acc.x * rinv;
    o.y = hv.y + acc.y * rinv;
    o.z = hv.z + acc.z * rinv;
    o.w = hv.w + acc.w * rinv;
    ((float4*)out)[row * 32 + lane] = o;

    if (lane == 0) {
        float dx = 0.f, dy = 0.f;
#pragma unroll
        for (int q = 0; q < 8; ++q) {
            dx = fmaf(eq[q], g_pdx[q * NN + row], dx);
            dy = fmaf(eq[q], g_pdy[q * NN + row], dy);
        }
        float2 xi = ((const float2*)xin)[row];
        float2 xo;
        xo.x = xi.x + dx * rinv;
        xo.y = xi.y + dy * rinv;
        ((float2*)(out + NN * HH))[row] = xo;
    }
}

// ---------------------------------------------------------------------------
extern "C" void kernel_launch(void* const* d_in, const int* in_sizes, int n_in,
                              void* d_out, int out_size) {
    (void)in_sizes; (void)n_in; (void)out_size;
    const float* h   = (const float*)d_in[0];
    const float* x   = (const float*)d_in[1];
    // d_in[2] = batch (unused, all zeros)
    const float* Wq  = (const float*)d_in[3];
    const float* bq  = (const float*)d_in[4];
    const float* Wk  = (const float*)d_in[5];
    const float* bk  = (const float*)d_in[6];
    const float* Wv  = (const float*)d_in[7];
    const float* bv  = (const float*)d_in[8];
    const float* We1 = (const float*)d_in[9];
    const float* be1 = (const float*)d_in[10];
    const float* We2 = (const float*)d_in[11];
    const float* be2 = (const float*)d_in[12];
    const float* Wc  = (const float*)d_in[13];
    const float* bc  = (const float*)d_in[14];
    float* out = (float*)d_out;

    static int smem_set = 0;
    if (!smem_set) {
        cudaFuncSetAttribute(attn_kernel, cudaFuncAttributeMaxDynamicSharedMemorySize,
                             SMEMF * 4);
        smem_set = 1;
    }

    qkv_kernel<<<384, 128>>>(h, x, Wq, bq, Wk, bk, Wv, bv,
                             We1, be1, We2, be2, Wc, bc);
    attn_kernel<<<256, 256, SMEMF * 4>>>(x);
    combine_kernel<<<128, 256>>>(h, x, out);
}

// round 8
// speedup vs baseline: 1.7359x; 1.0270x over previous
#include <cuda_runtime.h>

#define NN 1024
#define HH 128

typedef unsigned long long u64;
typedef unsigned int u32;

union F2U { u64 u; float2 f; };

__device__ __forceinline__ u64 fma2(u64 a, u64 b, u64 c) {
    u64 d; asm("fma.rn.f32x2 %0, %1, %2, %3;" : "=l"(d) : "l"(a), "l"(b), "l"(c)); return d;
}
__device__ __forceinline__ u64 add2(u64 a, u64 b) {
    u64 d; asm("add.rn.f32x2 %0, %1, %2;" : "=l"(d) : "l"(a), "l"(b)); return d;
}
__device__ __forceinline__ u64 relu2(u64 a) {
    F2U t; t.u = a;
    t.f.x = fmaxf(t.f.x, 0.f);
    t.f.y = fmaxf(t.f.y, 0.f);
    return t.u;
}
__device__ __forceinline__ u64 pack2(float x, float y) {
    F2U t; t.f.x = x; t.f.y = y; return t.u;
}
__device__ __forceinline__ float hsum2(u64 a, u64 b) {
    F2U x, y; x.u = a; y.u = b;
    return (x.f.x + x.f.y) + (y.f.x + y.f.y);
}
__device__ __forceinline__ u32 smem_u32(const void* p) {
    u32 a;
    asm("{ .reg .u64 t; cvta.to.shared.u64 t, %1; cvt.u32.u64 %0, t; }" : "=r"(a) : "l"(p));
    return a;
}
#define CP_ASYNC16(dst, src) \
    asm volatile("cp.async.cg.shared.global [%0], [%1], 16;" :: "r"(dst), "l"(src))
#define CP_COMMIT() asm volatile("cp.async.commit_group;" ::: "memory")
#define CP_WAIT0()  asm volatile("cp.async.wait_group 0;" ::: "memory")

// ---------------- device scratch (no allocations allowed) -------------------
__device__ __align__(16) float g_q[NN * HH];
__device__ __align__(16) float g_k[NN * HH];
__device__ __align__(16) float g_v[NN * HH];
__device__ __align__(16) float g_p[NN * HH];     // p_h(i) = a*x + b*y + c
__device__ __align__(16) float g_rn[NN * HH];    // -(a*x + b*y)
__device__ __align__(16) float g_g[HH];          // g = Wc @ We2
__device__ float g_c0d;                          // Wc . be2 + bc
// split-j partials (8 j-quarters)
__device__ __align__(16) float g_po[8 * NN * HH];  // unnormalized P@V partial
__device__ float g_pm[8 * NN];                     // local max
__device__ float g_pl[8 * NN];                     // local sum of exp
__device__ float g_pdx[8 * NN];
__device__ float g_pdy[8 * NN];

// ---------------------------------------------------------------------------
// QKV + p/rn + fold of the coord path.
// grid = 384 blocks (mat = bid>>7 in {q,k,v}, row-group = bid&127 -> 8 rows),
// 128 threads: thread o owns output column o of its matrix for 8 rows.
// W row is preloaded into registers (32 back-to-back LDG.128, MLP~32) so the
// L2/DRAM latency is paid once, not once per unroll chunk.
// ---------------------------------------------------------------------------
__global__ __launch_bounds__(128) void qkv_kernel(
    const float* __restrict__ hin, const float* __restrict__ xin,
    const float* __restrict__ Wq, const float* __restrict__ bq,
    const float* __restrict__ Wk, const float* __restrict__ bk,
    const float* __restrict__ Wv, const float* __restrict__ bv,
    const float* __restrict__ We1, const float* __restrict__ be1,
    const float* __restrict__ We2, const float* __restrict__ be2,
    const float* __restrict__ Wc,  const float* __restrict__ bc) {
    __shared__ __align__(16) float hs[8][HH];
    int mat = blockIdx.x >> 7;        // 0=q, 1=k, 2=v
    int r0  = (blockIdx.x & 127) * 8;

    for (int idx = threadIdx.x; idx < 8 * HH / 4; idx += 128)
        ((float4*)hs)[idx] = ((const float4*)(hin + r0 * HH))[idx];
    __syncthreads();

    int o = threadIdx.x;
    const float* W; float bias; float* dst; float scale;
    if (mat == 0)      { W = Wq + o * HH; bias = bq[o]; dst = g_q; scale = 0.08838834764831845f; }
    else if (mat == 1) { W = Wk + o * HH; bias = bk[o]; dst = g_k; scale = 1.0f; }
    else               { W = Wv + o * HH; bias = bv[o]; dst = g_v; scale = 1.0f; }

    // preload full W row into registers: 32 independent LDG.128
    const float4* W4 = (const float4*)W;
    float4 w[32];
#pragma unroll
    for (int c4 = 0; c4 < 32; ++c4) w[c4] = W4[c4];

    float acc[8];
#pragma unroll
    for (int r = 0; r < 8; ++r) acc[r] = bias;

#pragma unroll
    for (int c4 = 0; c4 < 32; ++c4) {
#pragma unroll
        for (int r = 0; r < 8; ++r) {
            float4 hv = ((const float4*)&hs[r][0])[c4];
            acc[r] = fmaf(hv.x, w[c4].x, acc[r]);
            acc[r] = fmaf(hv.y, w[c4].y, acc[r]);
            acc[r] = fmaf(hv.z, w[c4].z, acc[r]);
            acc[r] = fmaf(hv.w, w[c4].w, acc[r]);
        }
    }
#pragma unroll
    for (int r = 0; r < 8; ++r) dst[(r0 + r) * HH + o] = acc[r] * scale;

    // p / rn for these 8 rows (q-matrix blocks only)
    if (mat == 0) {
        float a = We1[2 * o], b = We1[2 * o + 1], c = be1[o];
#pragma unroll
        for (int r = 0; r < 8; ++r) {
            int row = r0 + r;
            float xx = xin[2 * row], yy = xin[2 * row + 1];
            float base = fmaf(a, xx, b * yy);
            g_p[row * HH + o]  = base + c;
            g_rn[row * HH + o] = -base;
        }
    }

    // fold (single block): g = Wc @ We2, c0 = Wc . be2 + bc
    if (blockIdx.x == 256) {          // first v block: all threads also fold
        float g = 0.f;
#pragma unroll 16
        for (int e = 0; e < HH; ++e) g = fmaf(Wc[e], We2[e * HH + o], g);
        g_g[o] = g;
        if (o == 0) {
            float c0 = bc[0];
#pragma unroll 16
            for (int e = 0; e < HH; ++e) c0 = fmaf(Wc[e], be2[e], c0);
            g_c0d = c0;
        }
    }
}

// ---------------------------------------------------------------------------
// Split-j fused attention + coord diffusion.  (round-4 proven version)
// grid = 256 blocks (32 row-groups x 8 j-quarters), 256 threads (8 warps).
// Each block: 32 rows x 128 j (4 tiles of 32 j). Warp w handles rows w*4..w*4+3.
// Smem layout (floats):
//   qs  [32][132] @ 0
//   ps  [32][132] @ 4224
//   ss  [128][36] @ 8448   (logits -> exp'd probs; [j][row])
//   gsm [128]     @ 13056
//   buf [2 tiles] @ 13184  (pass1: k double-buffer; pass2: v | rn)
// total 21632 floats = 86528 B -> 2 blocks/SM
// ---------------------------------------------------------------------------
#define TS 132
#define TILEF (32 * TS)
#define OFF_QS 0
#define OFF_PS 4224
#define OFF_SS 8448
#define OFF_G  13056
#define OFF_BUF 13184
#define SMEMF 21632

__device__ __forceinline__ void issue_tile(u32 dstbase, const float* __restrict__ src, int tid) {
#pragma unroll
    for (int l = 0; l < 4; ++l) {
        int c = tid + l * 256;
        int jr = c >> 5, c4 = c & 31;
        CP_ASYNC16(dstbase + (u32)((jr * TS + c4 * 4) * 4), src + jr * HH + c4 * 4);
    }
}

__global__ __launch_bounds__(256, 2) void attn_kernel(const float* __restrict__ xin) {
    extern __shared__ float sm[];
    int tid  = threadIdx.x;
    int warp = tid >> 5;
    int lane = tid & 31;
    int rg = blockIdx.x >> 3, jq = blockIdx.x & 7;
    int rbase = rg * 32, jbase = jq * 128;
    int r0 = warp * 4;

    // stage q, p for this block's 32 rows; g vector
    for (int idx = tid; idx < 32 * HH; idx += 256) {
        int r = idx >> 7, c = idx & 127;
        sm[OFF_QS + r * TS + c] = g_q[(rbase + r) * HH + c];
        sm[OFF_PS + r * TS + c] = g_p[(rbase + r) * HH + c];
    }
    if (tid < HH) sm[OFF_G + tid] = g_g[tid];

    u32 buf_u[2];
    buf_u[0] = smem_u32(sm + OFF_BUF);
    buf_u[1] = smem_u32(sm + OFF_BUF + TILEF);

    // ---- Pass 1: logits (k tiles double-buffered) ----
    issue_tile(buf_u[0], g_k + jbase * HH, tid);
    CP_COMMIT();

#pragma unroll
    for (int t = 0; t < 4; ++t) {
        CP_WAIT0();
        __syncthreads();                        // tile t visible; buffers free
        if (t < 3) {
            issue_tile(buf_u[(t + 1) & 1], g_k + (jbase + (t + 1) * 32) * HH, tid);
            CP_COMMIT();
        }
        const float* kb = sm + OFF_BUF + (t & 1) * TILEF;
        const ulonglong2* kp = (const ulonglong2*)(kb + lane * TS);
        const ulonglong2* q0 = (const ulonglong2*)(sm + OFF_QS + (r0 + 0) * TS);
        const ulonglong2* q1 = (const ulonglong2*)(sm + OFF_QS + (r0 + 1) * TS);
        const ulonglong2* q2 = (const ulonglong2*)(sm + OFF_QS + (r0 + 2) * TS);
        const ulonglong2* q3 = (const ulonglong2*)(sm + OFF_QS + (r0 + 3) * TS);
        u64 a00 = 0, a01 = 0, a10 = 0, a11 = 0, a20 = 0, a21 = 0, a30 = 0, a31 = 0;
#pragma unroll 8
        for (int m = 0; m < 32; ++m) {
            ulonglong2 kk = kp[m];
            ulonglong2 t0 = q0[m], t1 = q1[m], t2 = q2[m], t3 = q3[m];
            a00 = fma2(t0.x, kk.x, a00); a01 = fma2(t0.y, kk.y, a01);
            a10 = fma2(t1.x, kk.x, a10); a11 = fma2(t1.y, kk.y, a11);
            a20 = fma2(t2.x, kk.x, a20); a21 = fma2(t2.y, kk.y, a21);
            a30 = fma2(t3.x, kk.x, a30); a31 = fma2(t3.y, kk.y, a31);
        }
        float4 sv;
        sv.x = hsum2(a00, a01);
        sv.y = hsum2(a10, a11);
        sv.z = hsum2(a20, a21);
        sv.w = hsum2(a30, a31);
        *(float4*)(sm + OFF_SS + (t * 32 + lane) * 36 + r0) = sv;
    }

    // ---- local softmax (warp-private rows; unnormalized exp kept in ss) ----
    float m_r[4], l_r[4];
#pragma unroll
    for (int r = 0; r < 4; ++r) {
        int row = r0 + r;
        float s0 = sm[OFF_SS + (lane +  0) * 36 + row];
        float s1 = sm[OFF_SS + (lane + 32) * 36 + row];
        float s2 = sm[OFF_SS + (lane + 64) * 36 + row];
        float s3 = sm[OFF_SS + (lane + 96) * 36 + row];
        float mx = fmaxf(fmaxf(s0, s1), fmaxf(s2, s3));
#pragma unroll
        for (int off = 16; off; off >>= 1) mx = fmaxf(mx, __shfl_xor_sync(0xffffffffu, mx, off));
        float e0 = __expf(s0 - mx), e1 = __expf(s1 - mx);
        float e2 = __expf(s2 - mx), e3 = __expf(s3 - mx);
        sm[OFF_SS + (lane +  0) * 36 + row] = e0;
        sm[OFF_SS + (lane + 32) * 36 + row] = e1;
        sm[OFF_SS + (lane + 64) * 36 + row] = e2;
        sm[OFF_SS + (lane + 96) * 36 + row] = e3;
        float l = (e0 + e1) + (e2 + e3);
#pragma unroll
        for (int off = 16; off; off >>= 1) l += __shfl_xor_sync(0xffffffffu, l, off);
        m_r[r] = mx; l_r[r] = l;
    }

    // ---- Pass 2: P@V + coord (v in slot0, rn in slot1, single-buffered) ----
    float c0d = g_c0d;
    float2 xi[4];
#pragma unroll
    for (int r = 0; r < 4; ++r) xi[r] = ((const float2*)xin)[rbase + r0 + r];

    u64 o0a = 0, o0b = 0, o1a = 0, o1b = 0, o2a = 0, o2b = 0, o3a = 0, o3b = 0;
    float dxa[4] = {0.f, 0.f, 0.f, 0.f}, dya[4] = {0.f, 0.f, 0.f, 0.f};

    __syncthreads();   // all warps done with k buffers before v/rn overwrite

#pragma unroll
    for (int t = 0; t < 4; ++t) {
        issue_tile(buf_u[0], g_v  + (jbase + t * 32) * HH, tid);
        issue_tile(buf_u[1], g_rn + (jbase + t * 32) * HH, tid);
        CP_COMMIT();
        CP_WAIT0();
        __syncthreads();

        const float* vb  = sm + OFF_BUF;
        const float* rnb = sm + OFF_BUF + TILEF;

        // P @ V : lane = h-chunk (4 floats)
#pragma unroll 8
        for (int jj = 0; jj < 32; ++jj) {
            float4 p4 = *(const float4*)(sm + OFF_SS + (t * 32 + jj) * 36 + r0);
            ulonglong2 vv = *(const ulonglong2*)(vb + jj * TS + lane * 4);
            u64 pp;
            pp = pack2(p4.x, p4.x); o0a = fma2(pp, vv.x, o0a); o0b = fma2(pp, vv.y, o0b);
            pp = pack2(p4.y, p4.y); o1a = fma2(pp, vv.x, o1a); o1b = fma2(pp, vv.y, o1b);
            pp = pack2(p4.z, p4.z); o2a = fma2(pp, vv.x, o2a); o2b = fma2(pp, vv.y, o2b);
            pp = pack2(p4.w, p4.w); o3a = fma2(pp, vv.x, o3a); o3b = fma2(pp, vv.y, o3b);
        }

        // coord weights: lane = j
        const ulonglong2* rp = (const ulonglong2*)(rnb + lane * TS);
        const ulonglong2* g2 = (const ulonglong2*)(sm + OFF_G);
        const ulonglong2* p0 = (const ulonglong2*)(sm + OFF_PS + (r0 + 0) * TS);
        const ulonglong2* p1 = (const ulonglong2*)(sm + OFF_PS + (r0 + 1) * TS);
        const ulonglong2* p2 = (const ulonglong2*)(sm + OFF_PS + (r0 + 2) * TS);
        const ulonglong2* p3 = (const ulonglong2*)(sm + OFF_PS + (r0 + 3) * TS);
        u64 cA0 = 0, cB0 = 0, cA1 = 0, cB1 = 0, cA2 = 0, cB2 = 0, cA3 = 0, cB3 = 0;
#pragma unroll 8
        for (int mm = 0; mm < 32; ++mm) {
            ulonglong2 rr = rp[mm];
            ulonglong2 gg = g2[mm];
            ulonglong2 pA = p0[mm];
            cA0 = fma2(relu2(add2(pA.x, rr.x)), gg.x, cA0);
            cB0 = fma2(relu2(add2(pA.y, rr.y)), gg.y, cB0);
            ulonglong2 pB = p1[mm];
            cA1 = fma2(relu2(add2(pB.x, rr.x)), gg.x, cA1);
            cB1 = fma2(relu2(add2(pB.y, rr.y)), gg.y, cB1);
            ulonglong2 pC = p2[mm];
            cA2 = fma2(relu2(add2(pC.x, rr.x)), gg.x, cA2);
            cB2 = fma2(relu2(add2(pC.y, rr.y)), gg.y, cB2);
            ulonglong2 pD = p3[mm];
            cA3 = fma2(relu2(add2(pD.x, rr.x)), gg.x, cA3);
            cB3 = fma2(relu2(add2(pD.y, rr.y)), gg.y, cB3);
        }
        float cw0 = c0d + hsum2(cA0, cB0);
        float cw1 = c0d + hsum2(cA1, cB1);
        float cw2 = c0d + hsum2(cA2, cB2);
        float cw3 = c0d + hsum2(cA3, cB3);

        float4 p4j = *(const float4*)(sm + OFF_SS + (t * 32 + lane) * 36 + r0);
        float2 xj = __ldg((const float2*)xin + jbase + t * 32 + lane);
        float w;
        w = p4j.x * cw0; dxa[0] = fmaf(w, xi[0].x - xj.x, dxa[0]); dya[0] = fmaf(w, xi[0].y - xj.y, dya[0]);
        w = p4j.y * cw1; dxa[1] = fmaf(w, xi[1].x - xj.x, dxa[1]); dya[1] = fmaf(w, xi[1].y - xj.y, dya[1]);
        w = p4j.z * cw2; dxa[2] = fmaf(w, xi[2].x - xj.x, dxa[2]); dya[2] = fmaf(w, xi[2].y - xj.y, dya[2]);
        w = p4j.w * cw3; dxa[3] = fmaf(w, xi[3].x - xj.x, dxa[3]); dya[3] = fmaf(w, xi[3].y - xj.y, dya[3]);

        __syncthreads();   // tile fully consumed before next issue overwrites
    }

    // ---- write partials ----
    u64 oa[4] = {o0a, o1a, o2a, o3a};
    u64 ob[4] = {o0b, o1b, o2b, o3b};
#pragma unroll
    for (int r = 0; r < 4; ++r) {
        int row = rbase + r0 + r;
        F2U a, b; a.u = oa[r]; b.u = ob[r];
        float4 ov; ov.x = a.f.x; ov.y = a.f.y; ov.z = b.f.x; ov.w = b.f.y;
        ((float4*)g_po)[(jq * NN + row) * 32 + lane] = ov;
        float dx = dxa[r], dy = dya[r];
#pragma unroll
        for (int off = 16; off; off >>= 1) {
            dx += __shfl_xor_sync(0xffffffffu, dx, off);
            dy += __shfl_xor_sync(0xffffffffu, dy, off);
        }
        if (lane == 0) {
            g_pm[jq * NN + row]  = m_r[r];
            g_pl[jq * NN + row]  = l_r[r];
            g_pdx[jq * NN + row] = dx;
            g_pdy[jq * NN + row] = dy;
        }
    }
}

// ---------------------------------------------------------------------------
// Combine 8 j-quarter partials per row. grid 128 x 256 thr, warp = row.
// ---------------------------------------------------------------------------
__global__ __launch_bounds__(256) void combine_kernel(
    const float* __restrict__ hin, const float* __restrict__ xin,
    float* __restrict__ out) {
    int warp = threadIdx.x >> 5, lane = threadIdx.x & 31;
    int row = blockIdx.x * 8 + warp;

    float mq[8];
#pragma unroll
    for (int q = 0; q < 8; ++q) mq[q] = g_pm[q * NN + row];
    float M = mq[0];
#pragma unroll
    for (int q = 1; q < 8; ++q) M = fmaxf(M, mq[q]);
    float eq[8], L = 0.f;
#pragma unroll
    for (int q = 0; q < 8; ++q) {
        eq[q] = __expf(mq[q] - M);
        L = fmaf(eq[q], g_pl[q * NN + row], L);
    }
    float rinv = 1.f / L;

    float4 acc = make_float4(0.f, 0.f, 0.f, 0.f);
#pragma unroll
    for (int q = 0; q < 8; ++q) {
        float4 ov = ((const float4*)g_po)[(q * NN + row) * 32 + lane];
        acc.x = fmaf(eq[q], ov.x, acc.x);
        acc.y = fmaf(eq[q], ov.y, acc.y);
        acc.z = fmaf(eq[q], ov.z, acc.z);
        acc.w = fmaf(eq[q], ov.w, acc.w);
    }
    float4 hv = ((const float4*)hin)[row * 32 + lane];
    float4 o;
    o.x = hv.x + acc.x * rinv;
    o.y = hv.y + acc.y * rinv;
    o.z = hv.z + acc.z * rinv;
    o.w = hv.w + acc.w * rinv;
    ((float4*)out)[row * 32 + lane] = o;

    if (lane == 0) {
        float dx = 0.f, dy = 0.f;
#pragma unroll
        for (int q = 0; q < 8; ++q) {
            dx = fmaf(eq[q], g_pdx[q * NN + row], dx);
            dy = fmaf(eq[q], g_pdy[q * NN + row], dy);
        }
        float2 xi = ((const float2*)xin)[row];
        float2 xo;
        xo.x = xi.x + dx * rinv;
        xo.y = xi.y + dy * rinv;
        ((float2*)(out + NN * HH))[row] = xo;
    }
}

// ---------------------------------------------------------------------------
extern "C" void kernel_launch(void* const* d_in, const int* in_sizes, int n_in,
                              void* d_out, int out_size) {
    (void)in_sizes; (void)n_in; (void)out_size;
    const float* h   = (const float*)d_in[0];
    const float* x   = (const float*)d_in[1];
    // d_in[2] = batch (unused, all zeros)
    const float* Wq  = (const float*)d_in[3];
    const float* bq  = (const float*)d_in[4];
    const float* Wk  = (const float*)d_in[5];
    const float* bk  = (const float*)d_in[6];
    const float* Wv  = (const float*)d_in[7];
    const float* bv  = (const float*)d_in[8];
    const float* We1 = (const float*)d_in[9];
    const float* be1 = (const float*)d_in[10];
    const float* We2 = (const float*)d_in[11];
    const float* be2 = (const float*)d_in[12];
    const float* Wc  = (const float*)d_in[13];
    const float* bc  = (const float*)d_in[14];
    float* out = (float*)d_out;

    static int smem_set = 0;
    if (!smem_set) {
        cudaFuncSetAttribute(attn_kernel, cudaFuncAttributeMaxDynamicSharedMemorySize,
                             SMEMF * 4);
        smem_set = 1;
    }

    qkv_kernel<<<384, 128>>>(h, x, Wq, bq, Wk, bk, Wv, bv,
                             We1, be1, We2, be2, Wc, bc);
    attn_kernel<<<256, 256, SMEMF * 4>>>(x);
    combine_kernel<<<128, 256>>>(h, x, out);
}

// round 9
// speedup vs baseline: 1.7903x; 1.0314x over previous
#include <cuda_runtime.h>

#define NN 1024
#define HH 128

typedef unsigned long long u64;
typedef unsigned int u32;

union F2U { u64 u; float2 f; };

__device__ __forceinline__ u64 fma2(u64 a, u64 b, u64 c) {
    u64 d; asm("fma.rn.f32x2 %0, %1, %2, %3;" : "=l"(d) : "l"(a), "l"(b), "l"(c)); return d;
}
__device__ __forceinline__ u64 add2(u64 a, u64 b) {
    u64 d; asm("add.rn.f32x2 %0, %1, %2;" : "=l"(d) : "l"(a), "l"(b)); return d;
}
__device__ __forceinline__ u64 relu2(u64 a) {
    F2U t; t.u = a;
    t.f.x = fmaxf(t.f.x, 0.f);
    t.f.y = fmaxf(t.f.y, 0.f);
    return t.u;
}
__device__ __forceinline__ u64 pack2(float x, float y) {
    F2U t; t.f.x = x; t.f.y = y; return t.u;
}
__device__ __forceinline__ float hsum2(u64 a, u64 b) {
    F2U x, y; x.u = a; y.u = b;
    return (x.f.x + x.f.y) + (y.f.x + y.f.y);
}
__device__ __forceinline__ u32 smem_u32(const void* p) {
    u32 a;
    asm("{ .reg .u64 t; cvta.to.shared.u64 t, %1; cvt.u32.u64 %0, t; }" : "=r"(a) : "l"(p));
    return a;
}
#define CP_ASYNC16(dst, src) \
    asm volatile("cp.async.cg.shared.global [%0], [%1], 16;" :: "r"(dst), "l"(src))
#define CP_COMMIT() asm volatile("cp.async.commit_group;" ::: "memory")
#define CP_WAIT0()  asm volatile("cp.async.wait_group 0;" ::: "memory")

// ---------------- device scratch (no allocations allowed) -------------------
__device__ __align__(16) float g_q[NN * HH];
__device__ __align__(16) float g_k[NN * HH];
__device__ __align__(16) float g_v[NN * HH];
__device__ __align__(16) float g_p[NN * HH];     // p_h(i) = a*x + b*y + c
__device__ __align__(16) float g_rn[NN * HH];    // -(a*x + b*y)
__device__ __align__(16) float g_g[HH];          // g = Wc @ We2
__device__ float g_c0d;                          // Wc . be2 + bc
// split-j partials (8 j-quarters)
__device__ __align__(16) float g_po[8 * NN * HH];  // unnormalized P@V partial
__device__ float g_pm[8 * NN];                     // local max
__device__ float g_pl[8 * NN];                     // local sum of exp
__device__ float g_pdx[8 * NN];
__device__ float g_pdy[8 * NN];

// ---------------------------------------------------------------------------
// QKV + p/rn + fold of the coord path.
// grid = 384 blocks (mat = bid>>7 in {q,k,v}, row-group = bid&127 -> 8 rows),
// 128 threads: thread o owns output column o of its matrix for 8 rows.
// h rows AND the full W matrix are staged into smem via ONE cp.async batch:
// one latency window, then LDS-only compute (W stride-132 conflict-free,
// h reads broadcast).
// Dyn smem: hs[8][132] @ 0, ws[128][132] @ 1056 -> 17952 floats = 71808 B.
// ---------------------------------------------------------------------------
#define QKV_SMEMF 17952

__global__ __launch_bounds__(128) void qkv_kernel(
    const float* __restrict__ hin, const float* __restrict__ xin,
    const float* __restrict__ Wq, const float* __restrict__ bq,
    const float* __restrict__ Wk, const float* __restrict__ bk,
    const float* __restrict__ Wv, const float* __restrict__ bv,
    const float* __restrict__ We1, const float* __restrict__ be1,
    const float* __restrict__ We2, const float* __restrict__ be2,
    const float* __restrict__ Wc,  const float* __restrict__ bc) {
    extern __shared__ float qsm[];
    int tid = threadIdx.x;
    int mat = blockIdx.x >> 7;        // 0=q, 1=k, 2=v
    int r0  = (blockIdx.x & 127) * 8;

    const float* W; float bias; float* dst; float scale;
    int o = tid;
    if (mat == 0)      { W = Wq; bias = bq[o]; dst = g_q; scale = 0.08838834764831845f; }
    else if (mat == 1) { W = Wk; bias = bk[o]; dst = g_k; scale = 1.0f; }
    else               { W = Wv; bias = bv[o]; dst = g_v; scale = 1.0f; }

    u32 hs_u = smem_u32(qsm);
    u32 ws_u = smem_u32(qsm + 1056);

    // h: 8 rows x 128 = 256 float4 chunks, 2 per thread
#pragma unroll
    for (int l = 0; l < 2; ++l) {
        int idx = tid + l * 128;
        int r = idx >> 5, c4 = idx & 31;
        CP_ASYNC16(hs_u + (u32)((r * 132 + c4 * 4) * 4), hin + (r0 + r) * HH + c4 * 4);
    }
    // W: 128 rows x 32 chunks = 4096 float4 chunks, 32 per thread
#pragma unroll
    for (int l = 0; l < 32; ++l) {
        int idx = tid + l * 128;
        int r = idx >> 5, c4 = idx & 31;
        CP_ASYNC16(ws_u + (u32)((r * 132 + c4 * 4) * 4), W + r * HH + c4 * 4);
    }
    CP_COMMIT();
    CP_WAIT0();
    __syncthreads();

    const float4* wrow = (const float4*)(qsm + 1056 + o * 132);
    float acc[8];
#pragma unroll
    for (int r = 0; r < 8; ++r) acc[r] = bias;

#pragma unroll 8
    for (int c4 = 0; c4 < 32; ++c4) {
        float4 w = wrow[c4];
#pragma unroll
        for (int r = 0; r < 8; ++r) {
            float4 hv = ((const float4*)(qsm + r * 132))[c4];
            acc[r] = fmaf(hv.x, w.x, acc[r]);
            acc[r] = fmaf(hv.y, w.y, acc[r]);
            acc[r] = fmaf(hv.z, w.z, acc[r]);
            acc[r] = fmaf(hv.w, w.w, acc[r]);
        }
    }
#pragma unroll
    for (int r = 0; r < 8; ++r) dst[(r0 + r) * HH + o] = acc[r] * scale;

    // p / rn for these 8 rows (q-matrix blocks only)
    if (mat == 0) {
        float a = We1[2 * o], b = We1[2 * o + 1], c = be1[o];
#pragma unroll
        for (int r = 0; r < 8; ++r) {
            int row = r0 + r;
            float xx = xin[2 * row], yy = xin[2 * row + 1];
            float base = fmaf(a, xx, b * yy);
            g_p[row * HH + o]  = base + c;
            g_rn[row * HH + o] = -base;
        }
    }

    // fold (single block): g = Wc @ We2, c0 = Wc . be2 + bc
    if (blockIdx.x == 256) {
        float g = 0.f;
#pragma unroll 16
        for (int e = 0; e < HH; ++e) g = fmaf(Wc[e], We2[e * HH + o], g);
        g_g[o] = g;
        if (o == 0) {
            float c0 = bc[0];
#pragma unroll 16
            for (int e = 0; e < HH; ++e) c0 = fmaf(Wc[e], be2[e], c0);
            g_c0d = c0;
        }
    }
}

// ---------------------------------------------------------------------------
// Split-j fused attention + coord diffusion.
// grid = 256 blocks (32 row-groups x 8 j-quarters), 256 threads (8 warps).
// THREE pipelined tile passes, all with the proven wait0->sync->issue-next->
// compute structure: pass1 k-tiles (logits), pass2a v-tiles (PV), pass2b
// rn-tiles (coord). Pass1's t=3 slot prefetches v0; pass2a's t=3 prefetches
// rn0. Every tile load is hidden under the previous tile's compute.
// Smem layout (floats): qs[32][132]@0, ps[32][132]@4224, ss[128][36]@8448,
// g[128]@13056, buf 2 tiles @13184. total 21632 floats = 86528 B -> 2/SM.
// ---------------------------------------------------------------------------
#define TS 132
#define TILEF (32 * TS)
#define OFF_QS 0
#define OFF_PS 4224
#define OFF_SS 8448
#define OFF_G  13056
#define OFF_BUF 13184
#define SMEMF 21632

__device__ __forceinline__ void issue_tile(u32 dstbase, const float* __restrict__ src, int tid) {
#pragma unroll
    for (int l = 0; l < 4; ++l) {
        int c = tid + l * 256;
        int jr = c >> 5, c4 = c & 31;
        CP_ASYNC16(dstbase + (u32)((jr * TS + c4 * 4) * 4), src + jr * HH + c4 * 4);
    }
}

__global__ __launch_bounds__(256, 2) void attn_kernel(const float* __restrict__ xin) {
    extern __shared__ float sm[];
    int tid  = threadIdx.x;
    int warp = tid >> 5;
    int lane = tid & 31;
    int rg = blockIdx.x >> 3, jq = blockIdx.x & 7;
    int rbase = rg * 32, jbase = jq * 128;
    int r0 = warp * 4;

    // stage q, p for this block's 32 rows; g vector
    for (int idx = tid; idx < 32 * HH; idx += 256) {
        int r = idx >> 7, c = idx & 127;
        sm[OFF_QS + r * TS + c] = g_q[(rbase + r) * HH + c];
        sm[OFF_PS + r * TS + c] = g_p[(rbase + r) * HH + c];
    }
    if (tid < HH) sm[OFF_G + tid] = g_g[tid];

    u32 buf_u[2];
    buf_u[0] = smem_u32(sm + OFF_BUF);
    buf_u[1] = smem_u32(sm + OFF_BUF + TILEF);

    // ---- Pass 1: logits (k tiles double-buffered; t=3 prefetches v0) ----
    issue_tile(buf_u[0], g_k + jbase * HH, tid);
    CP_COMMIT();

#pragma unroll
    for (int t = 0; t < 4; ++t) {
        CP_WAIT0();
        __syncthreads();                        // tile t visible; other buf free
        if (t < 3) issue_tile(buf_u[(t + 1) & 1], g_k + (jbase + (t + 1) * 32) * HH, tid);
        else       issue_tile(buf_u[0], g_v + jbase * HH, tid);   // v0 -> buf0
        CP_COMMIT();
        const float* kb = sm + OFF_BUF + (t & 1) * TILEF;
        const ulonglong2* kp = (const ulonglong2*)(kb + lane * TS);
        const ulonglong2* q0 = (const ulonglong2*)(sm + OFF_QS + (r0 + 0) * TS);
        const ulonglong2* q1 = (const ulonglong2*)(sm + OFF_QS + (r0 + 1) * TS);
        const ulonglong2* q2 = (const ulonglong2*)(sm + OFF_QS + (r0 + 2) * TS);
        const ulonglong2* q3 = (const ulonglong2*)(sm + OFF_QS + (r0 + 3) * TS);
        u64 a00 = 0, a01 = 0, a10 = 0, a11 = 0, a20 = 0, a21 = 0, a30 = 0, a31 = 0;
#pragma unroll 8
        for (int m = 0; m < 32; ++m) {
            ulonglong2 kk = kp[m];
            ulonglong2 t0 = q0[m], t1 = q1[m], t2 = q2[m], t3 = q3[m];
            a00 = fma2(t0.x, kk.x, a00); a01 = fma2(t0.y, kk.y, a01);
            a10 = fma2(t1.x, kk.x, a10); a11 = fma2(t1.y, kk.y, a11);
            a20 = fma2(t2.x, kk.x, a20); a21 = fma2(t2.y, kk.y, a21);
            a30 = fma2(t3.x, kk.x, a30); a31 = fma2(t3.y, kk.y, a31);
        }
        float4 sv;
        sv.x = hsum2(a00, a01);
        sv.y = hsum2(a10, a11);
        sv.z = hsum2(a20, a21);
        sv.w = hsum2(a30, a31);
        *(float4*)(sm + OFF_SS + (t * 32 + lane) * 36 + r0) = sv;
    }

    // ---- local softmax (overlaps v0 load; warp-private rows) ----
    float m_r[4], l_r[4];
#pragma unroll
    for (int r = 0; r < 4; ++r) {
        int row = r0 + r;
        float s0 = sm[OFF_SS + (lane +  0) * 36 + row];
        float s1 = sm[OFF_SS + (lane + 32) * 36 + row];
        float s2 = sm[OFF_SS + (lane + 64) * 36 + row];
        float s3 = sm[OFF_SS + (lane + 96) * 36 + row];
        float mx = fmaxf(fmaxf(s0, s1), fmaxf(s2, s3));
#pragma unroll
        for (int off = 16; off; off >>= 1) mx = fmaxf(mx, __shfl_xor_sync(0xffffffffu, mx, off));
        float e0 = __expf(s0 - mx), e1 = __expf(s1 - mx);
        float e2 = __expf(s2 - mx), e3 = __expf(s3 - mx);
        sm[OFF_SS + (lane +  0) * 36 + row] = e0;
        sm[OFF_SS + (lane + 32) * 36 + row] = e1;
        sm[OFF_SS + (lane + 64) * 36 + row] = e2;
        sm[OFF_SS + (lane + 96) * 36 + row] = e3;
        float l = (e0 + e1) + (e2 + e3);
#pragma unroll
        for (int off = 16; off; off >>= 1) l += __shfl_xor_sync(0xffffffffu, l, off);
        m_r[r] = mx; l_r[r] = l;
    }

    // ---- Pass 2a: P@V (v tiles double-buffered; t=3 prefetches rn0) ----
    u64 o0a = 0, o0b = 0, o1a = 0, o1b = 0, o2a = 0, o2b = 0, o3a = 0, o3b = 0;

#pragma unroll
    for (int t = 0; t < 4; ++t) {
        CP_WAIT0();
        __syncthreads();
        if (t < 3) issue_tile(buf_u[(t + 1) & 1], g_v + (jbase + (t + 1) * 32) * HH, tid);
        else       issue_tile(buf_u[0], g_rn + jbase * HH, tid);  // rn0 -> buf0
        CP_COMMIT();
        const float* vb = sm + OFF_BUF + (t & 1) * TILEF;
#pragma unroll 8
        for (int jj = 0; jj < 32; ++jj) {
            float4 p4 = *(const float4*)(sm + OFF_SS + (t * 32 + jj) * 36 + r0);
            ulonglong2 vv = *(const ulonglong2*)(vb + jj * TS + lane * 4);
            u64 pp;
            pp = pack2(p4.x, p4.x); o0a = fma2(pp, vv.x, o0a); o0b = fma2(pp, vv.y, o0b);
            pp = pack2(p4.y, p4.y); o1a = fma2(pp, vv.x, o1a); o1b = fma2(pp, vv.y, o1b);
            pp = pack2(p4.z, p4.z); o2a = fma2(pp, vv.x, o2a); o2b = fma2(pp, vv.y, o2b);
            pp = pack2(p4.w, p4.w); o3a = fma2(pp, vv.x, o3a); o3b = fma2(pp, vv.y, o3b);
        }
    }

    // ---- Pass 2b: coord weights (rn tiles double-buffered) ----
    float c0d = g_c0d;
    float2 xi[4];
#pragma unroll
    for (int r = 0; r < 4; ++r) xi[r] = ((const float2*)xin)[rbase + r0 + r];
    float dxa[4] = {0.f, 0.f, 0.f, 0.f}, dya[4] = {0.f, 0.f, 0.f, 0.f};

#pragma unroll
    for (int t = 0; t < 4; ++t) {
        CP_WAIT0();
        __syncthreads();
        if (t < 3) {
            issue_tile(buf_u[(t + 1) & 1], g_rn + (jbase + (t + 1) * 32) * HH, tid);
            CP_COMMIT();
        }
        const float* rnb = sm + OFF_BUF + (t & 1) * TILEF;

        const ulonglong2* rp = (const ulonglong2*)(rnb + lane * TS);
        const ulonglong2* g2 = (const ulonglong2*)(sm + OFF_G);
        const ulonglong2* p0 = (const ulonglong2*)(sm + OFF_PS + (r0 + 0) * TS);
        const ulonglong2* p1 = (const ulonglong2*)(sm + OFF_PS + (r0 + 1) * TS);
        const ulonglong2* p2 = (const ulonglong2*)(sm + OFF_PS + (r0 + 2) * TS);
        const ulonglong2* p3 = (const ulonglong2*)(sm + OFF_PS + (r0 + 3) * TS);
        u64 cA0 = 0, cB0 = 0, cA1 = 0, cB1 = 0, cA2 = 0, cB2 = 0, cA3 = 0, cB3 = 0;
#pragma unroll 8
        for (int mm = 0; mm < 32; ++mm) {
            ulonglong2 rr = rp[mm];
            ulonglong2 gg = g2[mm];
            ulonglong2 pA = p0[mm];
            cA0 = fma2(relu2(add2(pA.x, rr.x)), gg.x, cA0);
            cB0 = fma2(relu2(add2(pA.y, rr.y)), gg.y, cB0);
            ulonglong2 pB = p1[mm];
            cA1 = fma2(relu2(add2(pB.x, rr.x)), gg.x, cA1);
            cB1 = fma2(relu2(add2(pB.y, rr.y)), gg.y, cB1);
            ulonglong2 pC = p2[mm];
            cA2 = fma2(relu2(add2(pC.x, rr.x)), gg.x, cA2);
            cB2 = fma2(relu2(add2(pC.y, rr.y)), gg.y, cB2);
            ulonglong2 pD = p3[mm];
            cA3 = fma2(relu2(add2(pD.x, rr.x)), gg.x, cA3);
            cB3 = fma2(relu2(add2(pD.y, rr.y)), gg.y, cB3);
        }
        float cw0 = c0d + hsum2(cA0, cB0);
        float cw1 = c0d + hsum2(cA1, cB1);
        float cw2 = c0d + hsum2(cA2, cB2);
        float cw3 = c0d + hsum2(cA3, cB3);

        float4 p4j = *(const float4*)(sm + OFF_SS + (t * 32 + lane) * 36 + r0);
        float2 xj = __ldg((const float2*)xin + jbase + t * 32 + lane);
        float w;
        w = p4j.x * cw0; dxa[0] = fmaf(w, xi[0].x - xj.x, dxa[0]); dya[0] = fmaf(w, xi[0].y - xj.y, dya[0]);
        w = p4j.y * cw1; dxa[1] = fmaf(w, xi[1].x - xj.x, dxa[1]); dya[1] = fmaf(w, xi[1].y - xj.y, dya[1]);
        w = p4j.z * cw2; dxa[2] = fmaf(w, xi[2].x - xj.x, dxa[2]); dya[2] = fmaf(w, xi[2].y - xj.y, dya[2]);
        w = p4j.w * cw3; dxa[3] = fmaf(w, xi[3].x - xj.x, dxa[3]); dya[3] = fmaf(w, xi[3].y - xj.y, dya[3]);
    }

    // ---- write partials ----
    u64 oa[4] = {o0a, o1a, o2a, o3a};
    u64 ob[4] = {o0b, o1b, o2b, o3b};
#pragma unroll
    for (int r = 0; r < 4; ++r) {
        int row = rbase + r0 + r;
        F2U a, b; a.u = oa[r]; b.u = ob[r];
        float4 ov; ov.x = a.f.x; ov.y = a.f.y; ov.z = b.f.x; ov.w = b.f.y;
        ((float4*)g_po)[(jq * NN + row) * 32 + lane] = ov;
        float dx = dxa[r], dy = dya[r];
#pragma unroll
        for (int off = 16; off; off >>= 1) {
            dx += __shfl_xor_sync(0xffffffffu, dx, off);
            dy += __shfl_xor_sync(0xffffffffu, dy, off);
        }
        if (lane == 0) {
            g_pm[jq * NN + row]  = m_r[r];
            g_pl[jq * NN + row]  = l_r[r];
            g_pdx[jq * NN + row] = dx;
            g_pdy[jq * NN + row] = dy;
        }
    }
}

// ---------------------------------------------------------------------------
// Combine 8 j-quarter partials per row. grid 128 x 256 thr, warp = row.
// ---------------------------------------------------------------------------
__global__ __launch_bounds__(256) void combine_kernel(
    const float* __restrict__ hin, const float* __restrict__ xin,
    float* __restrict__ out) {
    int warp = threadIdx.x >> 5, lane = threadIdx.x & 31;
    int row = blockIdx.x * 8 + warp;

    float mq[8];
#pragma unroll
    for (int q = 0; q < 8; ++q) mq[q] = g_pm[q * NN + row];
    float M = mq[0];
#pragma unroll
    for (int q = 1; q < 8; ++q) M = fmaxf(M, mq[q]);
    float eq[8], L = 0.f;
#pragma unroll
    for (int q = 0; q < 8; ++q) {
        eq[q] = __expf(mq[q] - M);
        L = fmaf(eq[q], g_pl[q * NN + row], L);
    }
    float rinv = 1.f / L;

    float4 acc = make_float4(0.f, 0.f, 0.f, 0.f);
#pragma unroll
    for (int q = 0; q < 8; ++q) {
        float4 ov = ((const float4*)g_po)[(q * NN + row) * 32 + lane];
        acc.x = fmaf(eq[q], ov.x, acc.x);
        acc.y = fmaf(eq[q], ov.y, acc.y);
        acc.z = fmaf(eq[q], ov.z, acc.z);
        acc.w = fmaf(eq[q], ov.w, acc.w);
    }
    float4 hv = ((const float4*)hin)[row * 32 + lane];
    float4 o;
    o.x = hv.x + acc.x * rinv;
    o.y = hv.y + acc.y * rinv;
    o.z = hv.z + acc.z * rinv;
    o.w = hv.w + acc.w * rinv;
    ((float4*)out)[row * 32 + lane] = o;

    if (lane == 0) {
        float dx = 0.f, dy = 0.f;
#pragma unroll
        for (int q = 0; q < 8; ++q) {
            dx = fmaf(eq[q], g_pdx[q * NN + row], dx);
            dy = fmaf(eq[q], g_pdy[q * NN + row], dy);
        }
        float2 xi = ((const float2*)xin)[row];
        float2 xo;
        xo.x = xi.x + dx * rinv;
        xo.y = xi.y + dy * rinv;
        ((float2*)(out + NN * HH))[row] = xo;
    }
}

// ---------------------------------------------------------------------------
extern "C" void kernel_launch(void* const* d_in, const int* in_sizes, int n_in,
                              void* d_out, int out_size) {
    (void)in_sizes; (void)n_in; (void)out_size;
    const float* h   = (const float*)d_in[0];
    const float* x   = (const float*)d_in[1];
    // d_in[2] = batch (unused, all zeros)
    const float* Wq  = (const float*)d_in[3];
    const float* bq  = (const float*)d_in[4];
    const float* Wk  = (const float*)d_in[5];
    const float* bk  = (const float*)d_in[6];
    const float* Wv  = (const float*)d_in[7];
    const float* bv  = (const float*)d_in[8];
    const float* We1 = (const float*)d_in[9];
    const float* be1 = (const float*)d_in[10];
    const float* We2 = (const float*)d_in[11];
    const float* be2 = (const float*)d_in[12];
    const float* Wc  = (const float*)d_in[13];
    const float* bc  = (const float*)d_in[14];
    float* out = (float*)d_out;

    static int smem_set = 0;
    if (!smem_set) {
        cudaFuncSetAttribute(attn_kernel, cudaFuncAttributeMaxDynamicSharedMemorySize,
                             SMEMF * 4);
        cudaFuncSetAttribute(qkv_kernel, cudaFuncAttributeMaxDynamicSharedMemorySize,
                             QKV_SMEMF * 4);
        smem_set = 1;
    }

    qkv_kernel<<<384, 128, QKV_SMEMF * 4>>>(h, x, Wq, bq, Wk, bk, Wv, bv,
                                            We1, be1, We2, be2, Wc, bc);
    attn_kernel<<<256, 256, SMEMF * 4>>>(x);
    combine_kernel<<<128, 256>>>(h, x, out);
}